// round 8
// baseline (speedup 1.0000x reference)
#include <cuda_runtime.h>
#include <math.h>
#include <cstdint>

#define TOTAL 4608
#define DMODEL 768
#define DFF 3072

// -------- scratch --------
__device__ float g_xn  [TOTAL * DMODEL];
__device__ float g_qkv [TOTAL * 3 * DMODEL];
__device__ float g_attn[TOTAL * DMODEL];
__device__ float g_x1  [TOTAL * DMODEL];
__device__ float g_h   [TOTAL * DFF];

__constant__ int c_cu[9]     = {0, 1024, 1920, 2688, 3328, 3840, 4288, 4544, 4608};
__constant__ int c_pfx128[9] = {0, 8, 15, 21, 26, 30, 34, 36, 37};

__device__ __forceinline__ uint32_t f2tf32(float x) {
    uint32_t u;
    asm("cvt.rna.tf32.f32 %0, %1;" : "=r"(u) : "f"(x));
    return u;
}

__device__ __forceinline__ float fexp2nc(float t) {
    float n = rintf(t);
    float f = t - n;
    float p = 8.98934e-3f;
    p = fmaf(p, f, 5.58263e-2f);
    p = fmaf(p, f, 2.40153e-1f);
    p = fmaf(p, f, 6.93147e-1f);
    p = fmaf(p, f, 1.0f);
    return __int_as_float(__float_as_int(p) + (((int)n) << 23));
}

#define MMA_TF32(d0,d1,d2,d3,a0,a1,a2,a3,b0,b1) \
    asm volatile("mma.sync.aligned.m16n8k8.row.col.f32.tf32.tf32.f32 " \
        "{%0,%1,%2,%3}, {%4,%5,%6,%7}, {%8,%9}, {%0,%1,%2,%3};" \
        : "+f"(d0), "+f"(d1), "+f"(d2), "+f"(d3) \
        : "r"(a0), "r"(a1), "r"(a2), "r"(a3), "r"(b0), "r"(b1))

// ---------------- LayerNorm: warp per row ----------------
__global__ __launch_bounds__(256) void ln_kernel(const float* __restrict__ x,
                                                 const float* __restrict__ w,
                                                 const float* __restrict__ b,
                                                 float* __restrict__ out) {
    int row  = blockIdx.x * 8 + (threadIdx.x >> 5);
    int lane = threadIdx.x & 31;
    const float* xr = x + (size_t)row * DMODEL;
    float4 v[6];
    float s = 0.f, ss = 0.f;
#pragma unroll
    for (int i = 0; i < 6; i++) {
        v[i] = *(const float4*)(xr + lane * 4 + i * 128);
        s  += v[i].x + v[i].y + v[i].z + v[i].w;
        ss += v[i].x * v[i].x + v[i].y * v[i].y + v[i].z * v[i].z + v[i].w * v[i].w;
    }
#pragma unroll
    for (int off = 16; off; off >>= 1) {
        s  += __shfl_xor_sync(0xffffffffu, s, off);
        ss += __shfl_xor_sync(0xffffffffu, ss, off);
    }
    float mu  = s * (1.f / DMODEL);
    float var = ss * (1.f / DMODEL) - mu * mu;
    float rstd = rsqrtf(var + 1e-6f);
    float* orow = out + (size_t)row * DMODEL;
#pragma unroll
    for (int i = 0; i < 6; i++) {
        int c = lane * 4 + i * 128;
        float4 wv = *(const float4*)(w + c);
        float4 bv = *(const float4*)(b + c);
        float4 o;
        o.x = (v[i].x - mu) * rstd * wv.x + bv.x;
        o.y = (v[i].y - mu) * rstd * wv.y + bv.y;
        o.z = (v[i].z - mu) * rstd * wv.z + bv.z;
        o.w = (v[i].w - mu) * rstd * wv.w + bv.w;
        *(float4*)(orow + c) = o;
    }
}

// ---------------- TF32 mma.sync GEMM v2: smem double-buffered, paired frags ----
// permuted K-chunk layout: idx(k) = 2*(k&3) + ((k>>2)&1) + 8*(k>>3), row stride 40
#define SKPP 40
#define GBUF (128 * SKPP)            // uints per matrix per buffer
#define G_SMEM_BYTES (4 * GBUF * 4)  // As0,Bs0,As1,Bs1

template <int EPI>
__global__ __launch_bounds__(256)
void gemm_mma(const float* __restrict__ A, const float* __restrict__ B,
              const float* __restrict__ bias, float* __restrict__ C,
              int K, int N, const float* __restrict__ res, const float* __restrict__ gamma) {
    extern __shared__ uint32_t gsm[];

    int tid = threadIdx.x, wid = tid >> 5, lane = tid & 31;
    int g = lane >> 2, t4 = lane & 3;
    int mw = (wid & 1) * 64;
    int nw = (wid >> 1) * 32;
    int bm = blockIdx.x * 128, bn = blockIdx.y * 128;

    float acc[4][4][4];
#pragma unroll
    for (int i = 0; i < 4; i++)
#pragma unroll
        for (int j = 0; j < 4; j++)
#pragma unroll
            for (int q = 0; q < 4; q++) acc[i][j][q] = 0.f;

    // staging map: quad jj -> fi = tid+256jj, row = fi>>3, m = fi&7
    // gmem cols for quad: k0 = (m>>1)*8 + (m&1)*2  -> float2 at k0, float2 at k0+4
    const float* Agp[4];
    const float* Bgp[4];
    uint32_t sdst[4];
#pragma unroll
    for (int jj = 0; jj < 4; jj++) {
        int fi = tid + 256 * jj;
        int row = fi >> 3, m = fi & 7;
        int k0 = (m >> 1) * 8 + (m & 1) * 2;
        Agp[jj] = A + (size_t)(bm + row) * K + k0;
        Bgp[jj] = B + (size_t)(bn + row) * K + k0;
        sdst[jj] = row * SKPP + 4 * m;
    }

    float2 aLo[4], aHi[4], bLo[4], bHi[4];
#pragma unroll
    for (int jj = 0; jj < 4; jj++) {
        aLo[jj] = *(const float2*)(Agp[jj]);
        aHi[jj] = *(const float2*)(Agp[jj] + 4);
        bLo[jj] = *(const float2*)(Bgp[jj]);
        bHi[jj] = *(const float2*)(Bgp[jj] + 4);
    }

    int NC = K >> 5;

    // STS chunk 0 -> buffer 0
#pragma unroll
    for (int jj = 0; jj < 4; jj++) {
        *(uint4*)&gsm[sdst[jj]] = make_uint4(f2tf32(aLo[jj].x), f2tf32(aHi[jj].x),
                                             f2tf32(aLo[jj].y), f2tf32(aHi[jj].y));
        *(uint4*)&gsm[GBUF + sdst[jj]] = make_uint4(f2tf32(bLo[jj].x), f2tf32(bHi[jj].x),
                                                    f2tf32(bLo[jj].y), f2tf32(bHi[jj].y));
    }
    // LDG chunk 1
    if (NC > 1) {
#pragma unroll
        for (int jj = 0; jj < 4; jj++) {
            Agp[jj] += 32; Bgp[jj] += 32;
            aLo[jj] = *(const float2*)(Agp[jj]);
            aHi[jj] = *(const float2*)(Agp[jj] + 4);
            bLo[jj] = *(const float2*)(Bgp[jj]);
            bHi[jj] = *(const float2*)(Bgp[jj] + 4);
        }
    }
    __syncthreads();

    for (int c = 0; c < NC; c++) {
        uint32_t* Asc = gsm + (c & 1) * (2 * GBUF);
        uint32_t* Bsc = Asc + GBUF;

        // STS chunk c+1 into other buffer (overlaps MMAs below)
        if (c + 1 < NC) {
            uint32_t* An = gsm + ((c + 1) & 1) * (2 * GBUF);
            uint32_t* Bn = An + GBUF;
#pragma unroll
            for (int jj = 0; jj < 4; jj++) {
                *(uint4*)&An[sdst[jj]] = make_uint4(f2tf32(aLo[jj].x), f2tf32(aHi[jj].x),
                                                    f2tf32(aLo[jj].y), f2tf32(aHi[jj].y));
                *(uint4*)&Bn[sdst[jj]] = make_uint4(f2tf32(bLo[jj].x), f2tf32(bHi[jj].x),
                                                    f2tf32(bLo[jj].y), f2tf32(bHi[jj].y));
            }
        }
        // LDG chunk c+2
        if (c + 2 < NC) {
#pragma unroll
            for (int jj = 0; jj < 4; jj++) {
                Agp[jj] += 32; Bgp[jj] += 32;
                aLo[jj] = *(const float2*)(Agp[jj]);
                aHi[jj] = *(const float2*)(Agp[jj] + 4);
                bLo[jj] = *(const float2*)(Bgp[jj]);
                bHi[jj] = *(const float2*)(Bgp[jj] + 4);
            }
        }

        // MMAs on chunk c: fragment pairs via LDS.64
#pragma unroll
        for (int s = 0; s < 4; s++) {
            int kk = 2 * t4 + 8 * s;
            uint2 bf2[4];
#pragma unroll
            for (int nt = 0; nt < 4; nt++)
                bf2[nt] = *(const uint2*)&Bsc[(nw + nt * 8 + g) * SKPP + kk];
#pragma unroll
            for (int mt = 0; mt < 4; mt++) {
                uint2 aL = *(const uint2*)&Asc[(mw + mt * 16 + g) * SKPP + kk];
                uint2 aH = *(const uint2*)&Asc[(mw + mt * 16 + 8 + g) * SKPP + kk];
#pragma unroll
                for (int nt = 0; nt < 4; nt++)
                    MMA_TF32(acc[mt][nt][0], acc[mt][nt][1], acc[mt][nt][2], acc[mt][nt][3],
                             aL.x, aH.x, aL.y, aH.y, bf2[nt].x, bf2[nt].y);
            }
        }
        __syncthreads();
    }

#pragma unroll
    for (int mt = 0; mt < 4; mt++) {
#pragma unroll
        for (int half = 0; half < 2; half++) {
            int r = bm + mw + mt * 16 + g + half * 8;
            float* Crow = C + (size_t)r * N;
            const float* resr = (EPI == 2) ? res + (size_t)r * N : nullptr;
#pragma unroll
            for (int nt = 0; nt < 4; nt++) {
                int cn = bn + nw + nt * 8 + 2 * t4;
                float v0 = acc[mt][nt][half * 2 + 0] + bias[cn];
                float v1 = acc[mt][nt][half * 2 + 1] + bias[cn + 1];
                if (EPI == 1) {
                    v0 = 0.5f * v0 * (1.f + erff(v0 * 0.70710678118654752f));
                    v1 = 0.5f * v1 * (1.f + erff(v1 * 0.70710678118654752f));
                }
                if (EPI == 2) {
                    v0 = resr[cn] + gamma[cn] * v0;
                    v1 = resr[cn + 1] + gamma[cn + 1] * v1;
                }
                *(float2*)(Crow + cn) = make_float2(v0, v1);
            }
        }
    }
}

// ---------------- Flash attention v3 (unchanged from R7) ----------------
#define KVROW 68
#define KVBUF (128 * KVROW)
#define A_SMEM2 (2 * KVBUF * 4)

__global__ __launch_bounds__(256) void attn_mma2(const float* __restrict__ qkv,
                                                 float* __restrict__ out) {
    extern __shared__ uint32_t sm[];

    int bx = blockIdx.x, h = blockIdx.y;
    int s = 0;
#pragma unroll
    for (int i = 1; i < 8; i++) s += (bx >= c_pfx128[i]) ? 1 : 0;
    int q0   = (bx - c_pfx128[s]) * 128;
    int base = c_cu[s];
    int L    = c_cu[s + 1] - base;

    int tid = threadIdx.x, wid = tid >> 5, lane = tid & 31;
    int g = lane >> 2, t4 = lane & 3;
    int ltok = tid >> 2;
    int dg   = (tid & 3) << 4;

    const float QSC = 0.18033688011112042f;
    uint32_t qa[8][4];
    {
        int r0 = q0 + wid * 16 + g, r1 = r0 + 8;
        bool v0 = r0 < L, v1 = r1 < L;
        const float* p0 = qkv + (size_t)(base + (v0 ? r0 : 0)) * 2304 + h * 64;
        const float* p1 = qkv + (size_t)(base + (v1 ? r1 : 0)) * 2304 + h * 64;
#pragma unroll
        for (int s8 = 0; s8 < 8; s8++) {
            int k0 = t4 + 8 * s8, k1 = k0 + 4;
            qa[s8][0] = v0 ? f2tf32(p0[k0] * QSC) : 0u;
            qa[s8][1] = v1 ? f2tf32(p1[k0] * QSC) : 0u;
            qa[s8][2] = v0 ? f2tf32(p0[k1] * QSC) : 0u;
            qa[s8][3] = v1 ? f2tf32(p1[k1] * QSC) : 0u;
        }
    }

    float l0 = 0.f, l1 = 0.f;
    float acco[8][4];
#pragma unroll
    for (int nt = 0; nt < 8; nt++)
#pragma unroll
        for (int q = 0; q < 4; q++) acco[nt][q] = 0.f;

    int nkt = (L + 63) >> 6;

    float4 kr[4], vr[4];
    bool kvalid;
    {
        int r = ltok;
        kvalid = r < L;
        const float* kp = qkv + (size_t)(base + (kvalid ? r : 0)) * 2304 + 768 + h * 64 + dg;
#pragma unroll
        for (int j = 0; j < 4; j++) {
            kr[j] = kvalid ? *(const float4*)(kp + j * 4) : make_float4(0, 0, 0, 0);
            vr[j] = kvalid ? *(const float4*)(kp + 768 + j * 4) : make_float4(0, 0, 0, 0);
        }
    }
    {
        uint32_t* Kb = sm;
        uint32_t* Vb = sm + 64 * KVROW;
        uint32_t kbase = ltok * KVROW + (dg >> 2);
#pragma unroll
        for (int c = 0; c < 4; c++) {
            float x0 = (&kr[0].x)[c], x1 = (&kr[1].x)[c], x2 = (&kr[2].x)[c], x3 = (&kr[3].x)[c];
            *(uint4*)&Kb[kbase + c * 16] = make_uint4(f2tf32(x0), f2tf32(x1), f2tf32(x2), f2tf32(x3));
        }
#pragma unroll
        for (int j = 0; j < 4; j++)
#pragma unroll
            for (int c = 0; c < 4; c++) {
                int idx = (4 * (j & 1) + c) * 8 + (dg >> 3) + (j >> 1);
                Vb[ltok * KVROW + idx] = f2tf32((&vr[j].x)[c]);
            }
    }

    for (int kt = 0; kt < nkt; kt++) {
        int kb = kt << 6;
        if (kt + 1 < nkt) {
            int r = kb + 64 + ltok;
            kvalid = r < L;
            const float* kp = qkv + (size_t)(base + (kvalid ? r : 0)) * 2304 + 768 + h * 64 + dg;
#pragma unroll
            for (int j = 0; j < 4; j++) {
                kr[j] = kvalid ? *(const float4*)(kp + j * 4) : make_float4(0, 0, 0, 0);
                vr[j] = kvalid ? *(const float4*)(kp + 768 + j * 4) : make_float4(0, 0, 0, 0);
            }
        }
        __syncthreads();

        uint32_t* Kb = sm + (kt & 1) * KVBUF;
        uint32_t* Vb = Kb + 64 * KVROW;

        float sc[8][4];
#pragma unroll
        for (int nt = 0; nt < 8; nt++) {
            sc[nt][0] = 0.f; sc[nt][1] = 0.f; sc[nt][2] = 0.f; sc[nt][3] = 0.f;
            const uint32_t* kp = &Kb[(nt * 8 + g) * KVROW + t4 * 16];
            uint4 k0 = *(const uint4*)(kp);
            uint4 k1 = *(const uint4*)(kp + 4);
            uint4 k2 = *(const uint4*)(kp + 8);
            uint4 k3 = *(const uint4*)(kp + 12);
            uint32_t kk[16] = {k0.x, k0.y, k0.z, k0.w, k1.x, k1.y, k1.z, k1.w,
                               k2.x, k2.y, k2.z, k2.w, k3.x, k3.y, k3.z, k3.w};
#pragma unroll
            for (int s8 = 0; s8 < 8; s8++)
                MMA_TF32(sc[nt][0], sc[nt][1], sc[nt][2], sc[nt][3],
                         qa[s8][0], qa[s8][1], qa[s8][2], qa[s8][3], kk[2 * s8], kk[2 * s8 + 1]);
        }

        if (kt + 1 < nkt) {
            uint32_t* Kn = sm + ((kt + 1) & 1) * KVBUF;
            uint32_t* Vn = Kn + 64 * KVROW;
            uint32_t kbase = ltok * KVROW + (dg >> 2);
#pragma unroll
            for (int c = 0; c < 4; c++) {
                float x0 = (&kr[0].x)[c], x1 = (&kr[1].x)[c], x2 = (&kr[2].x)[c], x3 = (&kr[3].x)[c];
                *(uint4*)&Kn[kbase + c * 16] = make_uint4(f2tf32(x0), f2tf32(x1), f2tf32(x2), f2tf32(x3));
            }
#pragma unroll
            for (int j = 0; j < 4; j++)
#pragma unroll
                for (int c = 0; c < 4; c++) {
                    int idx = (4 * (j & 1) + c) * 8 + (dg >> 3) + (j >> 1);
                    Vn[ltok * KVROW + idx] = f2tf32((&vr[j].x)[c]);
                }
        }

        if (kb + 64 > L) {
#pragma unroll
            for (int nt = 0; nt < 8; nt++) {
                int col = kb + nt * 8 + 2 * t4;
                if (col >= L)     { sc[nt][0] = -126.f; sc[nt][2] = -126.f; }
                if (col + 1 >= L) { sc[nt][1] = -126.f; sc[nt][3] = -126.f; }
            }
        }
#pragma unroll
        for (int nt = 0; nt < 8; nt++) {
            float p0 = fexp2nc(sc[nt][0]);
            float p1 = fexp2nc(sc[nt][1]);
            float p2 = fexp2nc(sc[nt][2]);
            float p3 = fexp2nc(sc[nt][3]);
            l0 += p0 + p1; l1 += p2 + p3;
            sc[nt][0] = p0; sc[nt][1] = p1; sc[nt][2] = p2; sc[nt][3] = p3;
        }

        int srcA = (lane & 28) | (t4 >> 1);
        bool odd = (t4 & 1);
#pragma unroll
        for (int s8 = 0; s8 < 8; s8++) {
            float u0 = __shfl_sync(0xffffffffu, sc[s8][0], srcA);
            float u1 = __shfl_sync(0xffffffffu, sc[s8][1], srcA);
            float u2 = __shfl_sync(0xffffffffu, sc[s8][2], srcA);
            float u3 = __shfl_sync(0xffffffffu, sc[s8][3], srcA);
            float w0 = __shfl_sync(0xffffffffu, sc[s8][0], srcA + 2);
            float w1 = __shfl_sync(0xffffffffu, sc[s8][1], srcA + 2);
            float w2 = __shfl_sync(0xffffffffu, sc[s8][2], srcA + 2);
            float w3 = __shfl_sync(0xffffffffu, sc[s8][3], srcA + 2);
            uint32_t pa0 = __float_as_uint(odd ? u1 : u0);
            uint32_t pa1 = __float_as_uint(odd ? u3 : u2);
            uint32_t pa2 = __float_as_uint(odd ? w1 : w0);
            uint32_t pa3 = __float_as_uint(odd ? w3 : w2);
            const uint32_t* v1p = &Vb[(t4 + 8 * s8) * KVROW + g * 8];
            const uint32_t* v2p = &Vb[(t4 + 4 + 8 * s8) * KVROW + g * 8];
            uint4 va = *(const uint4*)(v1p);
            uint4 vb2 = *(const uint4*)(v1p + 4);
            uint4 vc = *(const uint4*)(v2p);
            uint4 vd = *(const uint4*)(v2p + 4);
            uint32_t b0a[8] = {va.x, va.y, va.z, va.w, vb2.x, vb2.y, vb2.z, vb2.w};
            uint32_t b1a[8] = {vc.x, vc.y, vc.z, vc.w, vd.x, vd.y, vd.z, vd.w};
#pragma unroll
            for (int nt = 0; nt < 8; nt++)
                MMA_TF32(acco[nt][0], acco[nt][1], acco[nt][2], acco[nt][3],
                         pa0, pa1, pa2, pa3, b0a[nt], b1a[nt]);
        }
    }

#pragma unroll
    for (int off = 1; off <= 2; off <<= 1) {
        l0 += __shfl_xor_sync(0xffffffffu, l0, off);
        l1 += __shfl_xor_sync(0xffffffffu, l1, off);
    }
    float inv0 = 1.f / l0, inv1 = 1.f / l1;
    int r0 = q0 + wid * 16 + g, r1 = r0 + 8;
#pragma unroll
    for (int nt = 0; nt < 8; nt++) {
        int col = h * 64 + nt * 8 + 2 * t4;
        if (r0 < L)
            *(float2*)(out + (size_t)(base + r0) * 768 + col) =
                make_float2(acco[nt][0] * inv0, acco[nt][1] * inv0);
        if (r1 < L)
            *(float2*)(out + (size_t)(base + r1) * 768 + col) =
                make_float2(acco[nt][2] * inv1, acco[nt][3] * inv1);
    }
}

// ---------------- launch ----------------
extern "C" void kernel_launch(void* const* d_in, const int* in_sizes, int n_in,
                              void* d_out, int out_size) {
    const float* x      = (const float*)d_in[0];
    const float* n1w    = (const float*)d_in[1];
    const float* n1b    = (const float*)d_in[2];
    const float* qkv_w  = (const float*)d_in[3];
    const float* qkv_b  = (const float*)d_in[4];
    const float* proj_w = (const float*)d_in[5];
    const float* proj_b = (const float*)d_in[6];
    const float* ls1    = (const float*)d_in[7];
    const float* n2w    = (const float*)d_in[8];
    const float* n2b    = (const float*)d_in[9];
    const float* fc1_w  = (const float*)d_in[10];
    const float* fc1_b  = (const float*)d_in[11];
    const float* fc2_w  = (const float*)d_in[12];
    const float* fc2_b  = (const float*)d_in[13];
    const float* ls2    = (const float*)d_in[14];
    float* out = (float*)d_out;

    float *xn, *qkvb, *attn, *x1, *hb;
    cudaGetSymbolAddress((void**)&xn,   g_xn);
    cudaGetSymbolAddress((void**)&qkvb, g_qkv);
    cudaGetSymbolAddress((void**)&attn, g_attn);
    cudaGetSymbolAddress((void**)&x1,   g_x1);
    cudaGetSymbolAddress((void**)&hb,   g_h);

    cudaFuncSetAttribute(attn_mma2, cudaFuncAttributeMaxDynamicSharedMemorySize, A_SMEM2);
    cudaFuncSetAttribute(gemm_mma<0>, cudaFuncAttributeMaxDynamicSharedMemorySize, G_SMEM_BYTES);
    cudaFuncSetAttribute(gemm_mma<1>, cudaFuncAttributeMaxDynamicSharedMemorySize, G_SMEM_BYTES);
    cudaFuncSetAttribute(gemm_mma<2>, cudaFuncAttributeMaxDynamicSharedMemorySize, G_SMEM_BYTES);

    ln_kernel<<<576, 256>>>(x, n1w, n1b, xn);
    gemm_mma<0><<<dim3(36, 18), 256, G_SMEM_BYTES>>>(xn, qkv_w, qkv_b, qkvb, 768, 2304, nullptr, nullptr);
    attn_mma2<<<dim3(37, 12), 256, A_SMEM2>>>(qkvb, attn);
    gemm_mma<2><<<dim3(36, 6), 256, G_SMEM_BYTES>>>(attn, proj_w, proj_b, x1, 768, 768, x, ls1);
    ln_kernel<<<576, 256>>>(x1, n2w, n2b, xn);
    gemm_mma<1><<<dim3(36, 24), 256, G_SMEM_BYTES>>>(xn, fc1_w, fc1_b, hb, 768, 3072, nullptr, nullptr);
    gemm_mma<2><<<dim3(36, 6), 256, G_SMEM_BYTES>>>(hb, fc2_w, fc2_b, out, 3072, 768, x1, ls2);
}

// round 9
// speedup vs baseline: 1.1637x; 1.1637x over previous
#include <cuda_runtime.h>
#include <math.h>
#include <cstdint>

#define TOTAL 4608
#define DMODEL 768
#define DFF 3072

// -------- scratch --------
__device__ float g_xn  [TOTAL * DMODEL];
__device__ float g_qkv [TOTAL * 3 * DMODEL];
__device__ float g_attn[TOTAL * DMODEL];
__device__ float g_x1  [TOTAL * DMODEL];
__device__ float g_h   [TOTAL * DFF];

__constant__ int c_cu[9]     = {0, 1024, 1920, 2688, 3328, 3840, 4288, 4544, 4608};
__constant__ int c_pfx128[9] = {0, 8, 15, 21, 26, 30, 34, 36, 37};

__device__ __forceinline__ uint32_t f2tf32(float x) {
    uint32_t u;
    asm("cvt.rna.tf32.f32 %0, %1;" : "=r"(u) : "f"(x));
    return u;
}

__device__ __forceinline__ float fexp2nc(float t) {
    float n = rintf(t);
    float f = t - n;
    float p = 8.98934e-3f;
    p = fmaf(p, f, 5.58263e-2f);
    p = fmaf(p, f, 2.40153e-1f);
    p = fmaf(p, f, 6.93147e-1f);
    p = fmaf(p, f, 1.0f);
    return __int_as_float(__float_as_int(p) + (((int)n) << 23));
}

#define MMA_TF32(d0,d1,d2,d3,a0,a1,a2,a3,b0,b1) \
    asm volatile("mma.sync.aligned.m16n8k8.row.col.f32.tf32.tf32.f32 " \
        "{%0,%1,%2,%3}, {%4,%5,%6,%7}, {%8,%9}, {%0,%1,%2,%3};" \
        : "+f"(d0), "+f"(d1), "+f"(d2), "+f"(d3) \
        : "r"(a0), "r"(a1), "r"(a2), "r"(a3), "r"(b0), "r"(b1))

// ---------------- LayerNorm: warp per row ----------------
__global__ __launch_bounds__(256) void ln_kernel(const float* __restrict__ x,
                                                 const float* __restrict__ w,
                                                 const float* __restrict__ b,
                                                 float* __restrict__ out) {
    int row  = blockIdx.x * 8 + (threadIdx.x >> 5);
    int lane = threadIdx.x & 31;
    const float* xr = x + (size_t)row * DMODEL;
    float4 v[6];
    float s = 0.f, ss = 0.f;
#pragma unroll
    for (int i = 0; i < 6; i++) {
        v[i] = *(const float4*)(xr + lane * 4 + i * 128);
        s  += v[i].x + v[i].y + v[i].z + v[i].w;
        ss += v[i].x * v[i].x + v[i].y * v[i].y + v[i].z * v[i].z + v[i].w * v[i].w;
    }
#pragma unroll
    for (int off = 16; off; off >>= 1) {
        s  += __shfl_xor_sync(0xffffffffu, s, off);
        ss += __shfl_xor_sync(0xffffffffu, ss, off);
    }
    float mu  = s * (1.f / DMODEL);
    float var = ss * (1.f / DMODEL) - mu * mu;
    float rstd = rsqrtf(var + 1e-6f);
    float* orow = out + (size_t)row * DMODEL;
#pragma unroll
    for (int i = 0; i < 6; i++) {
        int c = lane * 4 + i * 128;
        float4 wv = *(const float4*)(w + c);
        float4 bv = *(const float4*)(b + c);
        float4 o;
        o.x = (v[i].x - mu) * rstd * wv.x + bv.x;
        o.y = (v[i].y - mu) * rstd * wv.y + bv.y;
        o.z = (v[i].z - mu) * rstd * wv.z + bv.z;
        o.w = (v[i].w - mu) * rstd * wv.w + bv.w;
        *(float4*)(orow + c) = o;
    }
}

// ---------------- TF32 mma.sync GEMM v3: 2 CTAs/SM, raw-bit tf32, simple loop ----
#define SKP 36

template <int EPI>
__global__ __launch_bounds__(256, 2)
void gemm_mma(const float* __restrict__ A, const float* __restrict__ B,
              const float* __restrict__ bias, float* __restrict__ C,
              int K, int N, const float* __restrict__ res, const float* __restrict__ gamma) {
    __shared__ uint32_t As[128 * SKP];
    __shared__ uint32_t Bs[128 * SKP];

    int tid = threadIdx.x, wid = tid >> 5, lane = tid & 31;
    int g = lane >> 2, t4 = lane & 3;
    int mw = (wid & 1) * 64;
    int nw = (wid >> 1) * 32;
    int bm = blockIdx.x * 128, bn = blockIdx.y * 128;

    float acc[4][4][4];
#pragma unroll
    for (int i = 0; i < 4; i++)
#pragma unroll
        for (int j = 0; j < 4; j++)
#pragma unroll
            for (int q = 0; q < 4; q++) acc[i][j][q] = 0.f;

    // staging map: fi = tid + 256*j -> row = fi>>3, c4 = fi&7 (uint4 column)
    const uint4* Ag[4];
    const uint4* Bg[4];
    uint32_t sdst[4];
#pragma unroll
    for (int j = 0; j < 4; j++) {
        int fi = tid + 256 * j;
        int row = fi >> 3, c4 = fi & 7;
        Ag[j] = (const uint4*)(A + (size_t)(bm + row) * K) + c4;
        Bg[j] = (const uint4*)(B + (size_t)(bn + row) * K) + c4;
        sdst[j] = row * SKP + c4 * 4;
    }

    int NC = K >> 5;
    for (int c = 0; c < NC; c++) {
        __syncthreads();
#pragma unroll
        for (int j = 0; j < 4; j++) {
            *(uint4*)&As[sdst[j]] = Ag[j][0];   // raw f32 bits; tensor core truncates to tf32
            *(uint4*)&Bs[sdst[j]] = Bg[j][0];
            Ag[j] += 8; Bg[j] += 8;
        }
        __syncthreads();
#pragma unroll
        for (int s = 0; s < 4; s++) {
            uint32_t af[4][4], bf[4][2];
#pragma unroll
            for (int mt = 0; mt < 4; mt++) {
                int r0 = (mw + mt * 16 + g) * SKP;
                int kk = t4 + 8 * s;
                af[mt][0] = As[r0 + kk];
                af[mt][1] = As[r0 + 8 * SKP + kk];
                af[mt][2] = As[r0 + kk + 4];
                af[mt][3] = As[r0 + 8 * SKP + kk + 4];
            }
#pragma unroll
            for (int nt = 0; nt < 4; nt++) {
                int r0 = (nw + nt * 8 + g) * SKP;
                int kk = t4 + 8 * s;
                bf[nt][0] = Bs[r0 + kk];
                bf[nt][1] = Bs[r0 + kk + 4];
            }
#pragma unroll
            for (int mt = 0; mt < 4; mt++)
#pragma unroll
                for (int nt = 0; nt < 4; nt++)
                    MMA_TF32(acc[mt][nt][0], acc[mt][nt][1], acc[mt][nt][2], acc[mt][nt][3],
                             af[mt][0], af[mt][1], af[mt][2], af[mt][3], bf[nt][0], bf[nt][1]);
        }
    }

#pragma unroll
    for (int mt = 0; mt < 4; mt++) {
#pragma unroll
        for (int half = 0; half < 2; half++) {
            int r = bm + mw + mt * 16 + g + half * 8;
            float* Crow = C + (size_t)r * N;
            const float* resr = (EPI == 2) ? res + (size_t)r * N : nullptr;
#pragma unroll
            for (int nt = 0; nt < 4; nt++) {
                int cn = bn + nw + nt * 8 + 2 * t4;
                float v0 = acc[mt][nt][half * 2 + 0] + bias[cn];
                float v1 = acc[mt][nt][half * 2 + 1] + bias[cn + 1];
                if (EPI == 1) {
                    v0 = 0.5f * v0 * (1.f + erff(v0 * 0.70710678118654752f));
                    v1 = 0.5f * v1 * (1.f + erff(v1 * 0.70710678118654752f));
                }
                if (EPI == 2) {
                    v0 = resr[cn] + gamma[cn] * v0;
                    v1 = resr[cn + 1] + gamma[cn + 1] * v1;
                }
                *(float2*)(Crow + cn) = make_float2(v0, v1);
            }
        }
    }
}

// ---------------- Flash attention v3 (unchanged from R7 best) ----------------
#define KVROW 68
#define KVBUF (128 * KVROW)
#define A_SMEM2 (2 * KVBUF * 4)

__global__ __launch_bounds__(256) void attn_mma2(const float* __restrict__ qkv,
                                                 float* __restrict__ out) {
    extern __shared__ uint32_t sm[];

    int bx = blockIdx.x, h = blockIdx.y;
    int s = 0;
#pragma unroll
    for (int i = 1; i < 8; i++) s += (bx >= c_pfx128[i]) ? 1 : 0;
    int q0   = (bx - c_pfx128[s]) * 128;
    int base = c_cu[s];
    int L    = c_cu[s + 1] - base;

    int tid = threadIdx.x, wid = tid >> 5, lane = tid & 31;
    int g = lane >> 2, t4 = lane & 3;
    int ltok = tid >> 2;
    int dg   = (tid & 3) << 4;

    const float QSC = 0.18033688011112042f;
    uint32_t qa[8][4];
    {
        int r0 = q0 + wid * 16 + g, r1 = r0 + 8;
        bool v0 = r0 < L, v1 = r1 < L;
        const float* p0 = qkv + (size_t)(base + (v0 ? r0 : 0)) * 2304 + h * 64;
        const float* p1 = qkv + (size_t)(base + (v1 ? r1 : 0)) * 2304 + h * 64;
#pragma unroll
        for (int s8 = 0; s8 < 8; s8++) {
            int k0 = t4 + 8 * s8, k1 = k0 + 4;
            qa[s8][0] = v0 ? f2tf32(p0[k0] * QSC) : 0u;
            qa[s8][1] = v1 ? f2tf32(p1[k0] * QSC) : 0u;
            qa[s8][2] = v0 ? f2tf32(p0[k1] * QSC) : 0u;
            qa[s8][3] = v1 ? f2tf32(p1[k1] * QSC) : 0u;
        }
    }

    float l0 = 0.f, l1 = 0.f;
    float acco[8][4];
#pragma unroll
    for (int nt = 0; nt < 8; nt++)
#pragma unroll
        for (int q = 0; q < 4; q++) acco[nt][q] = 0.f;

    int nkt = (L + 63) >> 6;

    float4 kr[4], vr[4];
    bool kvalid;
    {
        int r = ltok;
        kvalid = r < L;
        const float* kp = qkv + (size_t)(base + (kvalid ? r : 0)) * 2304 + 768 + h * 64 + dg;
#pragma unroll
        for (int j = 0; j < 4; j++) {
            kr[j] = kvalid ? *(const float4*)(kp + j * 4) : make_float4(0, 0, 0, 0);
            vr[j] = kvalid ? *(const float4*)(kp + 768 + j * 4) : make_float4(0, 0, 0, 0);
        }
    }
    {
        uint32_t* Kb = sm;
        uint32_t* Vb = sm + 64 * KVROW;
        uint32_t kbase = ltok * KVROW + (dg >> 2);
#pragma unroll
        for (int c = 0; c < 4; c++) {
            float x0 = (&kr[0].x)[c], x1 = (&kr[1].x)[c], x2 = (&kr[2].x)[c], x3 = (&kr[3].x)[c];
            *(uint4*)&Kb[kbase + c * 16] = make_uint4(f2tf32(x0), f2tf32(x1), f2tf32(x2), f2tf32(x3));
        }
#pragma unroll
        for (int j = 0; j < 4; j++)
#pragma unroll
            for (int c = 0; c < 4; c++) {
                int idx = (4 * (j & 1) + c) * 8 + (dg >> 3) + (j >> 1);
                Vb[ltok * KVROW + idx] = f2tf32((&vr[j].x)[c]);
            }
    }

    for (int kt = 0; kt < nkt; kt++) {
        int kb = kt << 6;
        if (kt + 1 < nkt) {
            int r = kb + 64 + ltok;
            kvalid = r < L;
            const float* kp = qkv + (size_t)(base + (kvalid ? r : 0)) * 2304 + 768 + h * 64 + dg;
#pragma unroll
            for (int j = 0; j < 4; j++) {
                kr[j] = kvalid ? *(const float4*)(kp + j * 4) : make_float4(0, 0, 0, 0);
                vr[j] = kvalid ? *(const float4*)(kp + 768 + j * 4) : make_float4(0, 0, 0, 0);
            }
        }
        __syncthreads();

        uint32_t* Kb = sm + (kt & 1) * KVBUF;
        uint32_t* Vb = Kb + 64 * KVROW;

        float sc[8][4];
#pragma unroll
        for (int nt = 0; nt < 8; nt++) {
            sc[nt][0] = 0.f; sc[nt][1] = 0.f; sc[nt][2] = 0.f; sc[nt][3] = 0.f;
            const uint32_t* kp = &Kb[(nt * 8 + g) * KVROW + t4 * 16];
            uint4 k0 = *(const uint4*)(kp);
            uint4 k1 = *(const uint4*)(kp + 4);
            uint4 k2 = *(const uint4*)(kp + 8);
            uint4 k3 = *(const uint4*)(kp + 12);
            uint32_t kk[16] = {k0.x, k0.y, k0.z, k0.w, k1.x, k1.y, k1.z, k1.w,
                               k2.x, k2.y, k2.z, k2.w, k3.x, k3.y, k3.z, k3.w};
#pragma unroll
            for (int s8 = 0; s8 < 8; s8++)
                MMA_TF32(sc[nt][0], sc[nt][1], sc[nt][2], sc[nt][3],
                         qa[s8][0], qa[s8][1], qa[s8][2], qa[s8][3], kk[2 * s8], kk[2 * s8 + 1]);
        }

        if (kt + 1 < nkt) {
            uint32_t* Kn = sm + ((kt + 1) & 1) * KVBUF;
            uint32_t* Vn = Kn + 64 * KVROW;
            uint32_t kbase = ltok * KVROW + (dg >> 2);
#pragma unroll
            for (int c = 0; c < 4; c++) {
                float x0 = (&kr[0].x)[c], x1 = (&kr[1].x)[c], x2 = (&kr[2].x)[c], x3 = (&kr[3].x)[c];
                *(uint4*)&Kn[kbase + c * 16] = make_uint4(f2tf32(x0), f2tf32(x1), f2tf32(x2), f2tf32(x3));
            }
#pragma unroll
            for (int j = 0; j < 4; j++)
#pragma unroll
                for (int c = 0; c < 4; c++) {
                    int idx = (4 * (j & 1) + c) * 8 + (dg >> 3) + (j >> 1);
                    Vn[ltok * KVROW + idx] = f2tf32((&vr[j].x)[c]);
                }
        }

        if (kb + 64 > L) {
#pragma unroll
            for (int nt = 0; nt < 8; nt++) {
                int col = kb + nt * 8 + 2 * t4;
                if (col >= L)     { sc[nt][0] = -126.f; sc[nt][2] = -126.f; }
                if (col + 1 >= L) { sc[nt][1] = -126.f; sc[nt][3] = -126.f; }
            }
        }
#pragma unroll
        for (int nt = 0; nt < 8; nt++) {
            float p0 = fexp2nc(sc[nt][0]);
            float p1 = fexp2nc(sc[nt][1]);
            float p2 = fexp2nc(sc[nt][2]);
            float p3 = fexp2nc(sc[nt][3]);
            l0 += p0 + p1; l1 += p2 + p3;
            sc[nt][0] = p0; sc[nt][1] = p1; sc[nt][2] = p2; sc[nt][3] = p3;
        }

        int srcA = (lane & 28) | (t4 >> 1);
        bool odd = (t4 & 1);
#pragma unroll
        for (int s8 = 0; s8 < 8; s8++) {
            float u0 = __shfl_sync(0xffffffffu, sc[s8][0], srcA);
            float u1 = __shfl_sync(0xffffffffu, sc[s8][1], srcA);
            float u2 = __shfl_sync(0xffffffffu, sc[s8][2], srcA);
            float u3 = __shfl_sync(0xffffffffu, sc[s8][3], srcA);
            float w0 = __shfl_sync(0xffffffffu, sc[s8][0], srcA + 2);
            float w1 = __shfl_sync(0xffffffffu, sc[s8][1], srcA + 2);
            float w2 = __shfl_sync(0xffffffffu, sc[s8][2], srcA + 2);
            float w3 = __shfl_sync(0xffffffffu, sc[s8][3], srcA + 2);
            uint32_t pa0 = __float_as_uint(odd ? u1 : u0);
            uint32_t pa1 = __float_as_uint(odd ? u3 : u2);
            uint32_t pa2 = __float_as_uint(odd ? w1 : w0);
            uint32_t pa3 = __float_as_uint(odd ? w3 : w2);
            const uint32_t* v1p = &Vb[(t4 + 8 * s8) * KVROW + g * 8];
            const uint32_t* v2p = &Vb[(t4 + 4 + 8 * s8) * KVROW + g * 8];
            uint4 va = *(const uint4*)(v1p);
            uint4 vb2 = *(const uint4*)(v1p + 4);
            uint4 vc = *(const uint4*)(v2p);
            uint4 vd = *(const uint4*)(v2p + 4);
            uint32_t b0a[8] = {va.x, va.y, va.z, va.w, vb2.x, vb2.y, vb2.z, vb2.w};
            uint32_t b1a[8] = {vc.x, vc.y, vc.z, vc.w, vd.x, vd.y, vd.z, vd.w};
#pragma unroll
            for (int nt = 0; nt < 8; nt++)
                MMA_TF32(acco[nt][0], acco[nt][1], acco[nt][2], acco[nt][3],
                         pa0, pa1, pa2, pa3, b0a[nt], b1a[nt]);
        }
    }

#pragma unroll
    for (int off = 1; off <= 2; off <<= 1) {
        l0 += __shfl_xor_sync(0xffffffffu, l0, off);
        l1 += __shfl_xor_sync(0xffffffffu, l1, off);
    }
    float inv0 = 1.f / l0, inv1 = 1.f / l1;
    int r0 = q0 + wid * 16 + g, r1 = r0 + 8;
#pragma unroll
    for (int nt = 0; nt < 8; nt++) {
        int col = h * 64 + nt * 8 + 2 * t4;
        if (r0 < L)
            *(float2*)(out + (size_t)(base + r0) * 768 + col) =
                make_float2(acco[nt][0] * inv0, acco[nt][1] * inv0);
        if (r1 < L)
            *(float2*)(out + (size_t)(base + r1) * 768 + col) =
                make_float2(acco[nt][2] * inv1, acco[nt][3] * inv1);
    }
}

// ---------------- launch ----------------
extern "C" void kernel_launch(void* const* d_in, const int* in_sizes, int n_in,
                              void* d_out, int out_size) {
    const float* x      = (const float*)d_in[0];
    const float* n1w    = (const float*)d_in[1];
    const float* n1b    = (const float*)d_in[2];
    const float* qkv_w  = (const float*)d_in[3];
    const float* qkv_b  = (const float*)d_in[4];
    const float* proj_w = (const float*)d_in[5];
    const float* proj_b = (const float*)d_in[6];
    const float* ls1    = (const float*)d_in[7];
    const float* n2w    = (const float*)d_in[8];
    const float* n2b    = (const float*)d_in[9];
    const float* fc1_w  = (const float*)d_in[10];
    const float* fc1_b  = (const float*)d_in[11];
    const float* fc2_w  = (const float*)d_in[12];
    const float* fc2_b  = (const float*)d_in[13];
    const float* ls2    = (const float*)d_in[14];
    float* out = (float*)d_out;

    float *xn, *qkvb, *attn, *x1, *hb;
    cudaGetSymbolAddress((void**)&xn,   g_xn);
    cudaGetSymbolAddress((void**)&qkvb, g_qkv);
    cudaGetSymbolAddress((void**)&attn, g_attn);
    cudaGetSymbolAddress((void**)&x1,   g_x1);
    cudaGetSymbolAddress((void**)&hb,   g_h);

    cudaFuncSetAttribute(attn_mma2, cudaFuncAttributeMaxDynamicSharedMemorySize, A_SMEM2);

    ln_kernel<<<576, 256>>>(x, n1w, n1b, xn);
    gemm_mma<0><<<dim3(36, 18), 256>>>(xn, qkv_w, qkv_b, qkvb, 768, 2304, nullptr, nullptr);
    attn_mma2<<<dim3(37, 12), 256, A_SMEM2>>>(qkvb, attn);
    gemm_mma<2><<<dim3(36, 6), 256>>>(attn, proj_w, proj_b, x1, 768, 768, x, ls1);
    ln_kernel<<<576, 256>>>(x1, n2w, n2b, xn);
    gemm_mma<1><<<dim3(36, 24), 256>>>(xn, fc1_w, fc1_b, hb, 768, 3072, nullptr, nullptr);
    gemm_mma<2><<<dim3(36, 6), 256>>>(hb, fc2_w, fc2_b, out, 3072, 768, x1, ls2);
}

// round 10
// speedup vs baseline: 1.4492x; 1.2453x over previous
#include <cuda_runtime.h>
#include <math.h>
#include <cstdint>

#define TOTAL 4608
#define DMODEL 768
#define DFF 3072

// -------- scratch --------
__device__ float g_xn  [TOTAL * DMODEL];
__device__ float g_qkv [TOTAL * 3 * DMODEL];
__device__ float g_attn[TOTAL * DMODEL];
__device__ float g_x1  [TOTAL * DMODEL];
__device__ float g_h   [TOTAL * DFF];

__constant__ int c_cu[9]     = {0, 1024, 1920, 2688, 3328, 3840, 4288, 4544, 4608};
__constant__ int c_pfx128[9] = {0, 8, 15, 21, 26, 30, 34, 36, 37};

__device__ __forceinline__ uint32_t f2tf32(float x) {
    uint32_t u;
    asm("cvt.rna.tf32.f32 %0, %1;" : "=r"(u) : "f"(x));
    return u;
}

// pack two f32 -> bf16x2 (lo = first arg), round-to-nearest
__device__ __forceinline__ uint32_t pack_bf16x2(float lo, float hi) {
    uint32_t u;
    asm("cvt.rn.bf16x2.f32 %0, %1, %2;" : "=r"(u) : "f"(hi), "f"(lo));
    return u;
}

__device__ __forceinline__ float fexp2nc(float t) {
    float n = rintf(t);
    float f = t - n;
    float p = 8.98934e-3f;
    p = fmaf(p, f, 5.58263e-2f);
    p = fmaf(p, f, 2.40153e-1f);
    p = fmaf(p, f, 6.93147e-1f);
    p = fmaf(p, f, 1.0f);
    return __int_as_float(__float_as_int(p) + (((int)n) << 23));
}

#define MMA_TF32(d0,d1,d2,d3,a0,a1,a2,a3,b0,b1) \
    asm volatile("mma.sync.aligned.m16n8k8.row.col.f32.tf32.tf32.f32 " \
        "{%0,%1,%2,%3}, {%4,%5,%6,%7}, {%8,%9}, {%0,%1,%2,%3};" \
        : "+f"(d0), "+f"(d1), "+f"(d2), "+f"(d3) \
        : "r"(a0), "r"(a1), "r"(a2), "r"(a3), "r"(b0), "r"(b1))

#define MMA_BF16(d0,d1,d2,d3,a0,a1,a2,a3,b0,b1) \
    asm volatile("mma.sync.aligned.m16n8k16.row.col.f32.bf16.bf16.f32 " \
        "{%0,%1,%2,%3}, {%4,%5,%6,%7}, {%8,%9}, {%0,%1,%2,%3};" \
        : "+f"(d0), "+f"(d1), "+f"(d2), "+f"(d3) \
        : "r"(a0), "r"(a1), "r"(a2), "r"(a3), "r"(b0), "r"(b1))

// ---------------- LayerNorm: warp per row ----------------
__global__ __launch_bounds__(256) void ln_kernel(const float* __restrict__ x,
                                                 const float* __restrict__ w,
                                                 const float* __restrict__ b,
                                                 float* __restrict__ out) {
    int row  = blockIdx.x * 8 + (threadIdx.x >> 5);
    int lane = threadIdx.x & 31;
    const float* xr = x + (size_t)row * DMODEL;
    float4 v[6];
    float s = 0.f, ss = 0.f;
#pragma unroll
    for (int i = 0; i < 6; i++) {
        v[i] = *(const float4*)(xr + lane * 4 + i * 128);
        s  += v[i].x + v[i].y + v[i].z + v[i].w;
        ss += v[i].x * v[i].x + v[i].y * v[i].y + v[i].z * v[i].z + v[i].w * v[i].w;
    }
#pragma unroll
    for (int off = 16; off; off >>= 1) {
        s  += __shfl_xor_sync(0xffffffffu, s, off);
        ss += __shfl_xor_sync(0xffffffffu, ss, off);
    }
    float mu  = s * (1.f / DMODEL);
    float var = ss * (1.f / DMODEL) - mu * mu;
    float rstd = rsqrtf(var + 1e-6f);
    float* orow = out + (size_t)row * DMODEL;
#pragma unroll
    for (int i = 0; i < 6; i++) {
        int c = lane * 4 + i * 128;
        float4 wv = *(const float4*)(w + c);
        float4 bv = *(const float4*)(b + c);
        float4 o;
        o.x = (v[i].x - mu) * rstd * wv.x + bv.x;
        o.y = (v[i].y - mu) * rstd * wv.y + bv.y;
        o.z = (v[i].z - mu) * rstd * wv.z + bv.z;
        o.w = (v[i].w - mu) * rstd * wv.w + bv.w;
        *(float4*)(orow + c) = o;
    }
}

// ---------------- BF16 mma.sync GEMM: 2 CTAs/SM, m16n8k16 ----------------
// K-chunk = 32 floats = 16 bf16x2 uints per row; row stride 20 uints (conflict-free)
#define SKB 20

template <int EPI>
__global__ __launch_bounds__(256, 2)
void gemm_mma(const float* __restrict__ A, const float* __restrict__ B,
              const float* __restrict__ bias, float* __restrict__ C,
              int K, int N, const float* __restrict__ res, const float* __restrict__ gamma) {
    __shared__ uint32_t As[128 * SKB];
    __shared__ uint32_t Bs[128 * SKB];

    int tid = threadIdx.x, wid = tid >> 5, lane = tid & 31;
    int g = lane >> 2, t4 = lane & 3;
    int mw = (wid & 1) * 64;
    int nw = (wid >> 1) * 32;
    int bm = blockIdx.x * 128, bn = blockIdx.y * 128;

    float acc[4][4][4];
#pragma unroll
    for (int i = 0; i < 4; i++)
#pragma unroll
        for (int j = 0; j < 4; j++)
#pragma unroll
            for (int q = 0; q < 4; q++) acc[i][j][q] = 0.f;

    // staging map: fi = tid + 256*j (j=0,1) -> row = fi>>2, q = fi&3
    // each thread converts 8 floats (2 float4) -> uint4 of bf16x2
    const float4* Ag[2];
    const float4* Bg[2];
    uint32_t sdst[2];
#pragma unroll
    for (int j = 0; j < 2; j++) {
        int fi = tid + 256 * j;
        int row = fi >> 2, q = fi & 3;
        Ag[j] = (const float4*)(A + (size_t)(bm + row) * K) + 2 * q;
        Bg[j] = (const float4*)(B + (size_t)(bn + row) * K) + 2 * q;
        sdst[j] = row * SKB + 4 * q;
    }

    int NC = K >> 5;
    for (int c = 0; c < NC; c++) {
        __syncthreads();
#pragma unroll
        for (int j = 0; j < 2; j++) {
            float4 a0 = Ag[j][0], a1 = Ag[j][1];
            float4 b0 = Bg[j][0], b1 = Bg[j][1];
            *(uint4*)&As[sdst[j]] = make_uint4(pack_bf16x2(a0.x, a0.y), pack_bf16x2(a0.z, a0.w),
                                               pack_bf16x2(a1.x, a1.y), pack_bf16x2(a1.z, a1.w));
            *(uint4*)&Bs[sdst[j]] = make_uint4(pack_bf16x2(b0.x, b0.y), pack_bf16x2(b0.z, b0.w),
                                               pack_bf16x2(b1.x, b1.y), pack_bf16x2(b1.z, b1.w));
            Ag[j] += 8; Bg[j] += 8;
        }
        __syncthreads();
#pragma unroll
        for (int s = 0; s < 2; s++) {          // two k16 steps per 32-float chunk
            int kk = t4 + 8 * s;
            uint32_t af[4][4], bf[4][2];
#pragma unroll
            for (int mt = 0; mt < 4; mt++) {
                int r0 = (mw + mt * 16 + g) * SKB;
                int r1 = r0 + 8 * SKB;
                af[mt][0] = As[r0 + kk];
                af[mt][1] = As[r1 + kk];
                af[mt][2] = As[r0 + kk + 4];
                af[mt][3] = As[r1 + kk + 4];
            }
#pragma unroll
            for (int nt = 0; nt < 4; nt++) {
                int rb = (nw + nt * 8 + g) * SKB;
                bf[nt][0] = Bs[rb + kk];
                bf[nt][1] = Bs[rb + kk + 4];
            }
#pragma unroll
            for (int mt = 0; mt < 4; mt++)
#pragma unroll
                for (int nt = 0; nt < 4; nt++)
                    MMA_BF16(acc[mt][nt][0], acc[mt][nt][1], acc[mt][nt][2], acc[mt][nt][3],
                             af[mt][0], af[mt][1], af[mt][2], af[mt][3], bf[nt][0], bf[nt][1]);
        }
    }

#pragma unroll
    for (int mt = 0; mt < 4; mt++) {
#pragma unroll
        for (int half = 0; half < 2; half++) {
            int r = bm + mw + mt * 16 + g + half * 8;
            float* Crow = C + (size_t)r * N;
            const float* resr = (EPI == 2) ? res + (size_t)r * N : nullptr;
#pragma unroll
            for (int nt = 0; nt < 4; nt++) {
                int cn = bn + nw + nt * 8 + 2 * t4;
                float v0 = acc[mt][nt][half * 2 + 0] + bias[cn];
                float v1 = acc[mt][nt][half * 2 + 1] + bias[cn + 1];
                if (EPI == 1) {
                    v0 = 0.5f * v0 * (1.f + erff(v0 * 0.70710678118654752f));
                    v1 = 0.5f * v1 * (1.f + erff(v1 * 0.70710678118654752f));
                }
                if (EPI == 2) {
                    v0 = resr[cn] + gamma[cn] * v0;
                    v1 = resr[cn + 1] + gamma[cn + 1] * v1;
                }
                *(float2*)(Crow + cn) = make_float2(v0, v1);
            }
        }
    }
}

// ---------------- Flash attention v3 (unchanged, tf32) ----------------
#define KVROW 68
#define KVBUF (128 * KVROW)
#define A_SMEM2 (2 * KVBUF * 4)

__global__ __launch_bounds__(256) void attn_mma2(const float* __restrict__ qkv,
                                                 float* __restrict__ out) {
    extern __shared__ uint32_t sm[];

    int bx = blockIdx.x, h = blockIdx.y;
    int s = 0;
#pragma unroll
    for (int i = 1; i < 8; i++) s += (bx >= c_pfx128[i]) ? 1 : 0;
    int q0   = (bx - c_pfx128[s]) * 128;
    int base = c_cu[s];
    int L    = c_cu[s + 1] - base;

    int tid = threadIdx.x, wid = tid >> 5, lane = tid & 31;
    int g = lane >> 2, t4 = lane & 3;
    int ltok = tid >> 2;
    int dg   = (tid & 3) << 4;

    const float QSC = 0.18033688011112042f;
    uint32_t qa[8][4];
    {
        int r0 = q0 + wid * 16 + g, r1 = r0 + 8;
        bool v0 = r0 < L, v1 = r1 < L;
        const float* p0 = qkv + (size_t)(base + (v0 ? r0 : 0)) * 2304 + h * 64;
        const float* p1 = qkv + (size_t)(base + (v1 ? r1 : 0)) * 2304 + h * 64;
#pragma unroll
        for (int s8 = 0; s8 < 8; s8++) {
            int k0 = t4 + 8 * s8, k1 = k0 + 4;
            qa[s8][0] = v0 ? f2tf32(p0[k0] * QSC) : 0u;
            qa[s8][1] = v1 ? f2tf32(p1[k0] * QSC) : 0u;
            qa[s8][2] = v0 ? f2tf32(p0[k1] * QSC) : 0u;
            qa[s8][3] = v1 ? f2tf32(p1[k1] * QSC) : 0u;
        }
    }

    float l0 = 0.f, l1 = 0.f;
    float acco[8][4];
#pragma unroll
    for (int nt = 0; nt < 8; nt++)
#pragma unroll
        for (int q = 0; q < 4; q++) acco[nt][q] = 0.f;

    int nkt = (L + 63) >> 6;

    float4 kr[4], vr[4];
    bool kvalid;
    {
        int r = ltok;
        kvalid = r < L;
        const float* kp = qkv + (size_t)(base + (kvalid ? r : 0)) * 2304 + 768 + h * 64 + dg;
#pragma unroll
        for (int j = 0; j < 4; j++) {
            kr[j] = kvalid ? *(const float4*)(kp + j * 4) : make_float4(0, 0, 0, 0);
            vr[j] = kvalid ? *(const float4*)(kp + 768 + j * 4) : make_float4(0, 0, 0, 0);
        }
    }
    {
        uint32_t* Kb = sm;
        uint32_t* Vb = sm + 64 * KVROW;
        uint32_t kbase = ltok * KVROW + (dg >> 2);
#pragma unroll
        for (int c = 0; c < 4; c++) {
            float x0 = (&kr[0].x)[c], x1 = (&kr[1].x)[c], x2 = (&kr[2].x)[c], x3 = (&kr[3].x)[c];
            *(uint4*)&Kb[kbase + c * 16] = make_uint4(f2tf32(x0), f2tf32(x1), f2tf32(x2), f2tf32(x3));
        }
#pragma unroll
        for (int j = 0; j < 4; j++)
#pragma unroll
            for (int c = 0; c < 4; c++) {
                int idx = (4 * (j & 1) + c) * 8 + (dg >> 3) + (j >> 1);
                Vb[ltok * KVROW + idx] = f2tf32((&vr[j].x)[c]);
            }
    }

    for (int kt = 0; kt < nkt; kt++) {
        int kb = kt << 6;
        if (kt + 1 < nkt) {
            int r = kb + 64 + ltok;
            kvalid = r < L;
            const float* kp = qkv + (size_t)(base + (kvalid ? r : 0)) * 2304 + 768 + h * 64 + dg;
#pragma unroll
            for (int j = 0; j < 4; j++) {
                kr[j] = kvalid ? *(const float4*)(kp + j * 4) : make_float4(0, 0, 0, 0);
                vr[j] = kvalid ? *(const float4*)(kp + 768 + j * 4) : make_float4(0, 0, 0, 0);
            }
        }
        __syncthreads();

        uint32_t* Kb = sm + (kt & 1) * KVBUF;
        uint32_t* Vb = Kb + 64 * KVROW;

        float sc[8][4];
#pragma unroll
        for (int nt = 0; nt < 8; nt++) {
            sc[nt][0] = 0.f; sc[nt][1] = 0.f; sc[nt][2] = 0.f; sc[nt][3] = 0.f;
            const uint32_t* kp = &Kb[(nt * 8 + g) * KVROW + t4 * 16];
            uint4 k0 = *(const uint4*)(kp);
            uint4 k1 = *(const uint4*)(kp + 4);
            uint4 k2 = *(const uint4*)(kp + 8);
            uint4 k3 = *(const uint4*)(kp + 12);
            uint32_t kk[16] = {k0.x, k0.y, k0.z, k0.w, k1.x, k1.y, k1.z, k1.w,
                               k2.x, k2.y, k2.z, k2.w, k3.x, k3.y, k3.z, k3.w};
#pragma unroll
            for (int s8 = 0; s8 < 8; s8++)
                MMA_TF32(sc[nt][0], sc[nt][1], sc[nt][2], sc[nt][3],
                         qa[s8][0], qa[s8][1], qa[s8][2], qa[s8][3], kk[2 * s8], kk[2 * s8 + 1]);
        }

        if (kt + 1 < nkt) {
            uint32_t* Kn = sm + ((kt + 1) & 1) * KVBUF;
            uint32_t* Vn = Kn + 64 * KVROW;
            uint32_t kbase = ltok * KVROW + (dg >> 2);
#pragma unroll
            for (int c = 0; c < 4; c++) {
                float x0 = (&kr[0].x)[c], x1 = (&kr[1].x)[c], x2 = (&kr[2].x)[c], x3 = (&kr[3].x)[c];
                *(uint4*)&Kn[kbase + c * 16] = make_uint4(f2tf32(x0), f2tf32(x1), f2tf32(x2), f2tf32(x3));
            }
#pragma unroll
            for (int j = 0; j < 4; j++)
#pragma unroll
                for (int c = 0; c < 4; c++) {
                    int idx = (4 * (j & 1) + c) * 8 + (dg >> 3) + (j >> 1);
                    Vn[ltok * KVROW + idx] = f2tf32((&vr[j].x)[c]);
                }
        }

        if (kb + 64 > L) {
#pragma unroll
            for (int nt = 0; nt < 8; nt++) {
                int col = kb + nt * 8 + 2 * t4;
                if (col >= L)     { sc[nt][0] = -126.f; sc[nt][2] = -126.f; }
                if (col + 1 >= L) { sc[nt][1] = -126.f; sc[nt][3] = -126.f; }
            }
        }
#pragma unroll
        for (int nt = 0; nt < 8; nt++) {
            float p0 = fexp2nc(sc[nt][0]);
            float p1 = fexp2nc(sc[nt][1]);
            float p2 = fexp2nc(sc[nt][2]);
            float p3 = fexp2nc(sc[nt][3]);
            l0 += p0 + p1; l1 += p2 + p3;
            sc[nt][0] = p0; sc[nt][1] = p1; sc[nt][2] = p2; sc[nt][3] = p3;
        }

        int srcA = (lane & 28) | (t4 >> 1);
        bool odd = (t4 & 1);
#pragma unroll
        for (int s8 = 0; s8 < 8; s8++) {
            float u0 = __shfl_sync(0xffffffffu, sc[s8][0], srcA);
            float u1 = __shfl_sync(0xffffffffu, sc[s8][1], srcA);
            float u2 = __shfl_sync(0xffffffffu, sc[s8][2], srcA);
            float u3 = __shfl_sync(0xffffffffu, sc[s8][3], srcA);
            float w0 = __shfl_sync(0xffffffffu, sc[s8][0], srcA + 2);
            float w1 = __shfl_sync(0xffffffffu, sc[s8][1], srcA + 2);
            float w2 = __shfl_sync(0xffffffffu, sc[s8][2], srcA + 2);
            float w3 = __shfl_sync(0xffffffffu, sc[s8][3], srcA + 2);
            uint32_t pa0 = __float_as_uint(odd ? u1 : u0);
            uint32_t pa1 = __float_as_uint(odd ? u3 : u2);
            uint32_t pa2 = __float_as_uint(odd ? w1 : w0);
            uint32_t pa3 = __float_as_uint(odd ? w3 : w2);
            const uint32_t* v1p = &Vb[(t4 + 8 * s8) * KVROW + g * 8];
            const uint32_t* v2p = &Vb[(t4 + 4 + 8 * s8) * KVROW + g * 8];
            uint4 va = *(const uint4*)(v1p);
            uint4 vb2 = *(const uint4*)(v1p + 4);
            uint4 vc = *(const uint4*)(v2p);
            uint4 vd = *(const uint4*)(v2p + 4);
            uint32_t b0a[8] = {va.x, va.y, va.z, va.w, vb2.x, vb2.y, vb2.z, vb2.w};
            uint32_t b1a[8] = {vc.x, vc.y, vc.z, vc.w, vd.x, vd.y, vd.z, vd.w};
#pragma unroll
            for (int nt = 0; nt < 8; nt++)
                MMA_TF32(acco[nt][0], acco[nt][1], acco[nt][2], acco[nt][3],
                         pa0, pa1, pa2, pa3, b0a[nt], b1a[nt]);
        }
    }

#pragma unroll
    for (int off = 1; off <= 2; off <<= 1) {
        l0 += __shfl_xor_sync(0xffffffffu, l0, off);
        l1 += __shfl_xor_sync(0xffffffffu, l1, off);
    }
    float inv0 = 1.f / l0, inv1 = 1.f / l1;
    int r0 = q0 + wid * 16 + g, r1 = r0 + 8;
#pragma unroll
    for (int nt = 0; nt < 8; nt++) {
        int col = h * 64 + nt * 8 + 2 * t4;
        if (r0 < L)
            *(float2*)(out + (size_t)(base + r0) * 768 + col) =
                make_float2(acco[nt][0] * inv0, acco[nt][1] * inv0);
        if (r1 < L)
            *(float2*)(out + (size_t)(base + r1) * 768 + col) =
                make_float2(acco[nt][2] * inv1, acco[nt][3] * inv1);
    }
}

// ---------------- launch ----------------
extern "C" void kernel_launch(void* const* d_in, const int* in_sizes, int n_in,
                              void* d_out, int out_size) {
    const float* x      = (const float*)d_in[0];
    const float* n1w    = (const float*)d_in[1];
    const float* n1b    = (const float*)d_in[2];
    const float* qkv_w  = (const float*)d_in[3];
    const float* qkv_b  = (const float*)d_in[4];
    const float* proj_w = (const float*)d_in[5];
    const float* proj_b = (const float*)d_in[6];
    const float* ls1    = (const float*)d_in[7];
    const float* n2w    = (const float*)d_in[8];
    const float* n2b    = (const float*)d_in[9];
    const float* fc1_w  = (const float*)d_in[10];
    const float* fc1_b  = (const float*)d_in[11];
    const float* fc2_w  = (const float*)d_in[12];
    const float* fc2_b  = (const float*)d_in[13];
    const float* ls2    = (const float*)d_in[14];
    float* out = (float*)d_out;

    float *xn, *qkvb, *attn, *x1, *hb;
    cudaGetSymbolAddress((void**)&xn,   g_xn);
    cudaGetSymbolAddress((void**)&qkvb, g_qkv);
    cudaGetSymbolAddress((void**)&attn, g_attn);
    cudaGetSymbolAddress((void**)&x1,   g_x1);
    cudaGetSymbolAddress((void**)&hb,   g_h);

    cudaFuncSetAttribute(attn_mma2, cudaFuncAttributeMaxDynamicSharedMemorySize, A_SMEM2);

    ln_kernel<<<576, 256>>>(x, n1w, n1b, xn);
    gemm_mma<0><<<dim3(36, 18), 256>>>(xn, qkv_w, qkv_b, qkvb, 768, 2304, nullptr, nullptr);
    attn_mma2<<<dim3(37, 12), 256, A_SMEM2>>>(qkvb, attn);
    gemm_mma<2><<<dim3(36, 6), 256>>>(attn, proj_w, proj_b, x1, 768, 768, x, ls1);
    ln_kernel<<<576, 256>>>(x1, n2w, n2b, xn);
    gemm_mma<1><<<dim3(36, 24), 256>>>(xn, fc1_w, fc1_b, hb, 768, 3072, nullptr, nullptr);
    gemm_mma<2><<<dim3(36, 6), 256>>>(hb, fc2_w, fc2_b, out, 3072, 768, x1, ls2);
}

// round 11
// speedup vs baseline: 1.4502x; 1.0007x over previous
#include <cuda_runtime.h>
#include <math.h>
#include <cstdint>

#define TOTAL 4608
#define DMODEL 768
#define DFF 3072

// -------- scratch --------
__device__ float g_xn  [TOTAL * DMODEL];
__device__ float g_qkv [TOTAL * 3 * DMODEL];
__device__ float g_attn[TOTAL * DMODEL];
__device__ float g_x1  [TOTAL * DMODEL];
__device__ float g_h   [TOTAL * DFF];

__constant__ int c_cu[9]     = {0, 1024, 1920, 2688, 3328, 3840, 4288, 4544, 4608};
__constant__ int c_pfx128[9] = {0, 8, 15, 21, 26, 30, 34, 36, 37};

__device__ __forceinline__ uint32_t f2tf32(float x) {
    uint32_t u;
    asm("cvt.rna.tf32.f32 %0, %1;" : "=r"(u) : "f"(x));
    return u;
}

// pack two f32 -> bf16x2 (lo = first arg), round-to-nearest
__device__ __forceinline__ uint32_t pack_bf16x2(float lo, float hi) {
    uint32_t u;
    asm("cvt.rn.bf16x2.f32 %0, %1, %2;" : "=r"(u) : "f"(hi), "f"(lo));
    return u;
}

__device__ __forceinline__ float fexp2nc(float t) {
    float n = rintf(t);
    float f = t - n;
    float p = 8.98934e-3f;
    p = fmaf(p, f, 5.58263e-2f);
    p = fmaf(p, f, 2.40153e-1f);
    p = fmaf(p, f, 6.93147e-1f);
    p = fmaf(p, f, 1.0f);
    return __int_as_float(__float_as_int(p) + (((int)n) << 23));
}

#define MMA_TF32(d0,d1,d2,d3,a0,a1,a2,a3,b0,b1) \
    asm volatile("mma.sync.aligned.m16n8k8.row.col.f32.tf32.tf32.f32 " \
        "{%0,%1,%2,%3}, {%4,%5,%6,%7}, {%8,%9}, {%0,%1,%2,%3};" \
        : "+f"(d0), "+f"(d1), "+f"(d2), "+f"(d3) \
        : "r"(a0), "r"(a1), "r"(a2), "r"(a3), "r"(b0), "r"(b1))

#define MMA_BF16(d0,d1,d2,d3,a0,a1,a2,a3,b0,b1) \
    asm volatile("mma.sync.aligned.m16n8k16.row.col.f32.bf16.bf16.f32 " \
        "{%0,%1,%2,%3}, {%4,%5,%6,%7}, {%8,%9}, {%0,%1,%2,%3};" \
        : "+f"(d0), "+f"(d1), "+f"(d2), "+f"(d3) \
        : "r"(a0), "r"(a1), "r"(a2), "r"(a3), "r"(b0), "r"(b1))

// ---------------- LayerNorm: warp per row ----------------
__global__ __launch_bounds__(256) void ln_kernel(const float* __restrict__ x,
                                                 const float* __restrict__ w,
                                                 const float* __restrict__ b,
                                                 float* __restrict__ out) {
    int row  = blockIdx.x * 8 + (threadIdx.x >> 5);
    int lane = threadIdx.x & 31;
    const float* xr = x + (size_t)row * DMODEL;
    float4 v[6];
    float s = 0.f, ss = 0.f;
#pragma unroll
    for (int i = 0; i < 6; i++) {
        v[i] = *(const float4*)(xr + lane * 4 + i * 128);
        s  += v[i].x + v[i].y + v[i].z + v[i].w;
        ss += v[i].x * v[i].x + v[i].y * v[i].y + v[i].z * v[i].z + v[i].w * v[i].w;
    }
#pragma unroll
    for (int off = 16; off; off >>= 1) {
        s  += __shfl_xor_sync(0xffffffffu, s, off);
        ss += __shfl_xor_sync(0xffffffffu, ss, off);
    }
    float mu  = s * (1.f / DMODEL);
    float var = ss * (1.f / DMODEL) - mu * mu;
    float rstd = rsqrtf(var + 1e-6f);
    float* orow = out + (size_t)row * DMODEL;
#pragma unroll
    for (int i = 0; i < 6; i++) {
        int c = lane * 4 + i * 128;
        float4 wv = *(const float4*)(w + c);
        float4 bv = *(const float4*)(b + c);
        float4 o;
        o.x = (v[i].x - mu) * rstd * wv.x + bv.x;
        o.y = (v[i].y - mu) * rstd * wv.y + bv.y;
        o.z = (v[i].z - mu) * rstd * wv.z + bv.z;
        o.w = (v[i].w - mu) * rstd * wv.w + bv.w;
        *(float4*)(orow + c) = o;
    }
}

// ---------------- BF16 mma.sync GEMM v2: BK=64, paired-frag layout, LDS.64 ----
// per 64-float row: 32 bf16x2 uints, permuted per 16-uint group:
//   pos(u) = 16*(u>>4) + 2*(u&3) + ((u>>2)&1) + 8*((u>>3)&1)
// so fragment pair (u, u+4) is adjacent -> one LDS.64. Row stride 40 uints:
// {g*40 mod 32} = {0,8,16,24} per 4-lane phase -> conflict-free LDS.64.
#define SKB 40

template <int EPI>
__global__ __launch_bounds__(256, 2)
void gemm_mma(const float* __restrict__ A, const float* __restrict__ B,
              const float* __restrict__ bias, float* __restrict__ C,
              int K, int N, const float* __restrict__ res, const float* __restrict__ gamma) {
    __shared__ uint32_t As[128 * SKB];
    __shared__ uint32_t Bs[128 * SKB];

    int tid = threadIdx.x, wid = tid >> 5, lane = tid & 31;
    int g = lane >> 2, t4 = lane & 3;
    int mw = (wid & 1) * 64;
    int nw = (wid >> 1) * 32;
    int bm = blockIdx.x * 128, bn = blockIdx.y * 128;

    float acc[4][4][4];
#pragma unroll
    for (int i = 0; i < 4; i++)
#pragma unroll
        for (int j = 0; j < 4; j++)
#pragma unroll
            for (int q = 0; q < 4; q++) acc[i][j][q] = 0.f;

    // staging map: fi = tid + 256*j -> row = fi>>3, q = fi&7 (which uint4 of 8)
    // gmem float4s at k_a = 32*(q>>2) + 16*((q>>1)&1) + 4*(q&1) and k_a+8
    const float* Arow[4];
    const float* Brow[4];
    uint32_t sdst[4];
#pragma unroll
    for (int j = 0; j < 4; j++) {
        int fi = tid + 256 * j;
        int row = fi >> 3, q = fi & 7;
        int ka = ((q >> 2) << 5) + (((q >> 1) & 1) << 4) + ((q & 1) << 2);
        Arow[j] = A + (size_t)(bm + row) * K + ka;
        Brow[j] = B + (size_t)(bn + row) * K + ka;
        sdst[j] = row * SKB + 4 * q;
    }

    int NC = K >> 6;
    for (int c = 0; c < NC; c++) {
        __syncthreads();
#pragma unroll
        for (int j = 0; j < 4; j++) {
            float4 a0 = *(const float4*)(Arow[j]);
            float4 a1 = *(const float4*)(Arow[j] + 8);
            float4 b0 = *(const float4*)(Brow[j]);
            float4 b1 = *(const float4*)(Brow[j] + 8);
            *(uint4*)&As[sdst[j]] = make_uint4(pack_bf16x2(a0.x, a0.y), pack_bf16x2(a1.x, a1.y),
                                               pack_bf16x2(a0.z, a0.w), pack_bf16x2(a1.z, a1.w));
            *(uint4*)&Bs[sdst[j]] = make_uint4(pack_bf16x2(b0.x, b0.y), pack_bf16x2(b1.x, b1.y),
                                               pack_bf16x2(b0.z, b0.w), pack_bf16x2(b1.z, b1.w));
            Arow[j] += 64; Brow[j] += 64;
        }
        __syncthreads();
#pragma unroll
        for (int s = 0; s < 4; s++) {          // four k16 steps per 64-float chunk
            int kp = ((s >> 1) << 4) + ((s & 1) << 3) + 2 * t4;
            uint2 bfp[4];
#pragma unroll
            for (int nt = 0; nt < 4; nt++)
                bfp[nt] = *(const uint2*)&Bs[(nw + nt * 8 + g) * SKB + kp];
#pragma unroll
            for (int mt = 0; mt < 4; mt++) {
                uint2 aL = *(const uint2*)&As[(mw + mt * 16 + g) * SKB + kp];
                uint2 aH = *(const uint2*)&As[(mw + mt * 16 + 8 + g) * SKB + kp];
#pragma unroll
                for (int nt = 0; nt < 4; nt++)
                    MMA_BF16(acc[mt][nt][0], acc[mt][nt][1], acc[mt][nt][2], acc[mt][nt][3],
                             aL.x, aH.x, aL.y, aH.y, bfp[nt].x, bfp[nt].y);
            }
        }
    }

#pragma unroll
    for (int mt = 0; mt < 4; mt++) {
#pragma unroll
        for (int half = 0; half < 2; half++) {
            int r = bm + mw + mt * 16 + g + half * 8;
            float* Crow = C + (size_t)r * N;
            const float* resr = (EPI == 2) ? res + (size_t)r * N : nullptr;
#pragma unroll
            for (int nt = 0; nt < 4; nt++) {
                int cn = bn + nw + nt * 8 + 2 * t4;
                float v0 = acc[mt][nt][half * 2 + 0] + bias[cn];
                float v1 = acc[mt][nt][half * 2 + 1] + bias[cn + 1];
                if (EPI == 1) {
                    v0 = 0.5f * v0 * (1.f + erff(v0 * 0.70710678118654752f));
                    v1 = 0.5f * v1 * (1.f + erff(v1 * 0.70710678118654752f));
                }
                if (EPI == 2) {
                    v0 = resr[cn] + gamma[cn] * v0;
                    v1 = resr[cn + 1] + gamma[cn + 1] * v1;
                }
                *(float2*)(Crow + cn) = make_float2(v0, v1);
            }
        }
    }
}

// ---------------- Flash attention v3 (unchanged, tf32) ----------------
#define KVROW 68
#define KVBUF (128 * KVROW)
#define A_SMEM2 (2 * KVBUF * 4)

__global__ __launch_bounds__(256) void attn_mma2(const float* __restrict__ qkv,
                                                 float* __restrict__ out) {
    extern __shared__ uint32_t sm[];

    int bx = blockIdx.x, h = blockIdx.y;
    int s = 0;
#pragma unroll
    for (int i = 1; i < 8; i++) s += (bx >= c_pfx128[i]) ? 1 : 0;
    int q0   = (bx - c_pfx128[s]) * 128;
    int base = c_cu[s];
    int L    = c_cu[s + 1] - base;

    int tid = threadIdx.x, wid = tid >> 5, lane = tid & 31;
    int g = lane >> 2, t4 = lane & 3;
    int ltok = tid >> 2;
    int dg   = (tid & 3) << 4;

    const float QSC = 0.18033688011112042f;
    uint32_t qa[8][4];
    {
        int r0 = q0 + wid * 16 + g, r1 = r0 + 8;
        bool v0 = r0 < L, v1 = r1 < L;
        const float* p0 = qkv + (size_t)(base + (v0 ? r0 : 0)) * 2304 + h * 64;
        const float* p1 = qkv + (size_t)(base + (v1 ? r1 : 0)) * 2304 + h * 64;
#pragma unroll
        for (int s8 = 0; s8 < 8; s8++) {
            int k0 = t4 + 8 * s8, k1 = k0 + 4;
            qa[s8][0] = v0 ? f2tf32(p0[k0] * QSC) : 0u;
            qa[s8][1] = v1 ? f2tf32(p1[k0] * QSC) : 0u;
            qa[s8][2] = v0 ? f2tf32(p0[k1] * QSC) : 0u;
            qa[s8][3] = v1 ? f2tf32(p1[k1] * QSC) : 0u;
        }
    }

    float l0 = 0.f, l1 = 0.f;
    float acco[8][4];
#pragma unroll
    for (int nt = 0; nt < 8; nt++)
#pragma unroll
        for (int q = 0; q < 4; q++) acco[nt][q] = 0.f;

    int nkt = (L + 63) >> 6;

    float4 kr[4], vr[4];
    bool kvalid;
    {
        int r = ltok;
        kvalid = r < L;
        const float* kp = qkv + (size_t)(base + (kvalid ? r : 0)) * 2304 + 768 + h * 64 + dg;
#pragma unroll
        for (int j = 0; j < 4; j++) {
            kr[j] = kvalid ? *(const float4*)(kp + j * 4) : make_float4(0, 0, 0, 0);
            vr[j] = kvalid ? *(const float4*)(kp + 768 + j * 4) : make_float4(0, 0, 0, 0);
        }
    }
    {
        uint32_t* Kb = sm;
        uint32_t* Vb = sm + 64 * KVROW;
        uint32_t kbase = ltok * KVROW + (dg >> 2);
#pragma unroll
        for (int c = 0; c < 4; c++) {
            float x0 = (&kr[0].x)[c], x1 = (&kr[1].x)[c], x2 = (&kr[2].x)[c], x3 = (&kr[3].x)[c];
            *(uint4*)&Kb[kbase + c * 16] = make_uint4(f2tf32(x0), f2tf32(x1), f2tf32(x2), f2tf32(x3));
        }
#pragma unroll
        for (int j = 0; j < 4; j++)
#pragma unroll
            for (int c = 0; c < 4; c++) {
                int idx = (4 * (j & 1) + c) * 8 + (dg >> 3) + (j >> 1);
                Vb[ltok * KVROW + idx] = f2tf32((&vr[j].x)[c]);
            }
    }

    for (int kt = 0; kt < nkt; kt++) {
        int kb = kt << 6;
        if (kt + 1 < nkt) {
            int r = kb + 64 + ltok;
            kvalid = r < L;
            const float* kp = qkv + (size_t)(base + (kvalid ? r : 0)) * 2304 + 768 + h * 64 + dg;
#pragma unroll
            for (int j = 0; j < 4; j++) {
                kr[j] = kvalid ? *(const float4*)(kp + j * 4) : make_float4(0, 0, 0, 0);
                vr[j] = kvalid ? *(const float4*)(kp + 768 + j * 4) : make_float4(0, 0, 0, 0);
            }
        }
        __syncthreads();

        uint32_t* Kb = sm + (kt & 1) * KVBUF;
        uint32_t* Vb = Kb + 64 * KVROW;

        float sc[8][4];
#pragma unroll
        for (int nt = 0; nt < 8; nt++) {
            sc[nt][0] = 0.f; sc[nt][1] = 0.f; sc[nt][2] = 0.f; sc[nt][3] = 0.f;
            const uint32_t* kp = &Kb[(nt * 8 + g) * KVROW + t4 * 16];
            uint4 k0 = *(const uint4*)(kp);
            uint4 k1 = *(const uint4*)(kp + 4);
            uint4 k2 = *(const uint4*)(kp + 8);
            uint4 k3 = *(const uint4*)(kp + 12);
            uint32_t kk[16] = {k0.x, k0.y, k0.z, k0.w, k1.x, k1.y, k1.z, k1.w,
                               k2.x, k2.y, k2.z, k2.w, k3.x, k3.y, k3.z, k3.w};
#pragma unroll
            for (int s8 = 0; s8 < 8; s8++)
                MMA_TF32(sc[nt][0], sc[nt][1], sc[nt][2], sc[nt][3],
                         qa[s8][0], qa[s8][1], qa[s8][2], qa[s8][3], kk[2 * s8], kk[2 * s8 + 1]);
        }

        if (kt + 1 < nkt) {
            uint32_t* Kn = sm + ((kt + 1) & 1) * KVBUF;
            uint32_t* Vn = Kn + 64 * KVROW;
            uint32_t kbase = ltok * KVROW + (dg >> 2);
#pragma unroll
            for (int c = 0; c < 4; c++) {
                float x0 = (&kr[0].x)[c], x1 = (&kr[1].x)[c], x2 = (&kr[2].x)[c], x3 = (&kr[3].x)[c];
                *(uint4*)&Kn[kbase + c * 16] = make_uint4(f2tf32(x0), f2tf32(x1), f2tf32(x2), f2tf32(x3));
            }
#pragma unroll
            for (int j = 0; j < 4; j++)
#pragma unroll
                for (int c = 0; c < 4; c++) {
                    int idx = (4 * (j & 1) + c) * 8 + (dg >> 3) + (j >> 1);
                    Vn[ltok * KVROW + idx] = f2tf32((&vr[j].x)[c]);
                }
        }

        if (kb + 64 > L) {
#pragma unroll
            for (int nt = 0; nt < 8; nt++) {
                int col = kb + nt * 8 + 2 * t4;
                if (col >= L)     { sc[nt][0] = -126.f; sc[nt][2] = -126.f; }
                if (col + 1 >= L) { sc[nt][1] = -126.f; sc[nt][3] = -126.f; }
            }
        }
#pragma unroll
        for (int nt = 0; nt < 8; nt++) {
            float p0 = fexp2nc(sc[nt][0]);
            float p1 = fexp2nc(sc[nt][1]);
            float p2 = fexp2nc(sc[nt][2]);
            float p3 = fexp2nc(sc[nt][3]);
            l0 += p0 + p1; l1 += p2 + p3;
            sc[nt][0] = p0; sc[nt][1] = p1; sc[nt][2] = p2; sc[nt][3] = p3;
        }

        int srcA = (lane & 28) | (t4 >> 1);
        bool odd = (t4 & 1);
#pragma unroll
        for (int s8 = 0; s8 < 8; s8++) {
            float u0 = __shfl_sync(0xffffffffu, sc[s8][0], srcA);
            float u1 = __shfl_sync(0xffffffffu, sc[s8][1], srcA);
            float u2 = __shfl_sync(0xffffffffu, sc[s8][2], srcA);
            float u3 = __shfl_sync(0xffffffffu, sc[s8][3], srcA);
            float w0 = __shfl_sync(0xffffffffu, sc[s8][0], srcA + 2);
            float w1 = __shfl_sync(0xffffffffu, sc[s8][1], srcA + 2);
            float w2 = __shfl_sync(0xffffffffu, sc[s8][2], srcA + 2);
            float w3 = __shfl_sync(0xffffffffu, sc[s8][3], srcA + 2);
            uint32_t pa0 = __float_as_uint(odd ? u1 : u0);
            uint32_t pa1 = __float_as_uint(odd ? u3 : u2);
            uint32_t pa2 = __float_as_uint(odd ? w1 : w0);
            uint32_t pa3 = __float_as_uint(odd ? w3 : w2);
            const uint32_t* v1p = &Vb[(t4 + 8 * s8) * KVROW + g * 8];
            const uint32_t* v2p = &Vb[(t4 + 4 + 8 * s8) * KVROW + g * 8];
            uint4 va = *(const uint4*)(v1p);
            uint4 vb2 = *(const uint4*)(v1p + 4);
            uint4 vc = *(const uint4*)(v2p);
            uint4 vd = *(const uint4*)(v2p + 4);
            uint32_t b0a[8] = {va.x, va.y, va.z, va.w, vb2.x, vb2.y, vb2.z, vb2.w};
            uint32_t b1a[8] = {vc.x, vc.y, vc.z, vc.w, vd.x, vd.y, vd.z, vd.w};
#pragma unroll
            for (int nt = 0; nt < 8; nt++)
                MMA_TF32(acco[nt][0], acco[nt][1], acco[nt][2], acco[nt][3],
                         pa0, pa1, pa2, pa3, b0a[nt], b1a[nt]);
        }
    }

#pragma unroll
    for (int off = 1; off <= 2; off <<= 1) {
        l0 += __shfl_xor_sync(0xffffffffu, l0, off);
        l1 += __shfl_xor_sync(0xffffffffu, l1, off);
    }
    float inv0 = 1.f / l0, inv1 = 1.f / l1;
    int r0 = q0 + wid * 16 + g, r1 = r0 + 8;
#pragma unroll
    for (int nt = 0; nt < 8; nt++) {
        int col = h * 64 + nt * 8 + 2 * t4;
        if (r0 < L)
            *(float2*)(out + (size_t)(base + r0) * 768 + col) =
                make_float2(acco[nt][0] * inv0, acco[nt][1] * inv0);
        if (r1 < L)
            *(float2*)(out + (size_t)(base + r1) * 768 + col) =
                make_float2(acco[nt][2] * inv1, acco[nt][3] * inv1);
    }
}

// ---------------- launch ----------------
extern "C" void kernel_launch(void* const* d_in, const int* in_sizes, int n_in,
                              void* d_out, int out_size) {
    const float* x      = (const float*)d_in[0];
    const float* n1w    = (const float*)d_in[1];
    const float* n1b    = (const float*)d_in[2];
    const float* qkv_w  = (const float*)d_in[3];
    const float* qkv_b  = (const float*)d_in[4];
    const float* proj_w = (const float*)d_in[5];
    const float* proj_b = (const float*)d_in[6];
    const float* ls1    = (const float*)d_in[7];
    const float* n2w    = (const float*)d_in[8];
    const float* n2b    = (const float*)d_in[9];
    const float* fc1_w  = (const float*)d_in[10];
    const float* fc1_b  = (const float*)d_in[11];
    const float* fc2_w  = (const float*)d_in[12];
    const float* fc2_b  = (const float*)d_in[13];
    const float* ls2    = (const float*)d_in[14];
    float* out = (float*)d_out;

    float *xn, *qkvb, *attn, *x1, *hb;
    cudaGetSymbolAddress((void**)&xn,   g_xn);
    cudaGetSymbolAddress((void**)&qkvb, g_qkv);
    cudaGetSymbolAddress((void**)&attn, g_attn);
    cudaGetSymbolAddress((void**)&x1,   g_x1);
    cudaGetSymbolAddress((void**)&hb,   g_h);

    cudaFuncSetAttribute(attn_mma2, cudaFuncAttributeMaxDynamicSharedMemorySize, A_SMEM2);

    ln_kernel<<<576, 256>>>(x, n1w, n1b, xn);
    gemm_mma<0><<<dim3(36, 18), 256>>>(xn, qkv_w, qkv_b, qkvb, 768, 2304, nullptr, nullptr);
    attn_mma2<<<dim3(37, 12), 256, A_SMEM2>>>(qkvb, attn);
    gemm_mma<2><<<dim3(36, 6), 256>>>(attn, proj_w, proj_b, x1, 768, 768, x, ls1);
    ln_kernel<<<576, 256>>>(x1, n2w, n2b, xn);
    gemm_mma<1><<<dim3(36, 24), 256>>>(xn, fc1_w, fc1_b, hb, 768, 3072, nullptr, nullptr);
    gemm_mma<2><<<dim3(36, 6), 256>>>(hb, fc2_w, fc2_b, out, 3072, 768, x1, ls2);
}

// round 12
// speedup vs baseline: 1.8267x; 1.2596x over previous
#include <cuda_runtime.h>
#include <math.h>
#include <cstdint>

#define TOTAL 4608
#define DMODEL 768
#define DFF 3072

// -------- scratch --------
__device__ uint32_t g_xnb  [TOTAL * 384];    // bf16x2 LN output
__device__ float    g_qkv  [TOTAL * 2304];   // f32 qkv (attention input)
__device__ uint32_t g_attnb[TOTAL * 384];    // bf16x2 attention output
__device__ float    g_x1   [TOTAL * 768];
__device__ uint32_t g_hb   [TOTAL * 1536];   // bf16x2 GELU output
__device__ uint32_t g_wq   [884736];
__device__ uint32_t g_wp   [294912];
__device__ uint32_t g_w1   [1179648];
__device__ uint32_t g_w2   [1179648];

__constant__ int c_cu[9]     = {0, 1024, 1920, 2688, 3328, 3840, 4288, 4544, 4608};
__constant__ int c_pfx128[9] = {0, 8, 15, 21, 26, 30, 34, 36, 37};

__device__ __forceinline__ uint32_t smem_u32(const void* p) {
    uint32_t a;
    asm("{ .reg .u64 t; cvta.to.shared.u64 t, %1; cvt.u32.u64 %0, t; }" : "=r"(a) : "l"(p));
    return a;
}
__device__ __forceinline__ uint32_t f2tf32(float x) {
    uint32_t u;
    asm("cvt.rna.tf32.f32 %0, %1;" : "=r"(u) : "f"(x));
    return u;
}
__device__ __forceinline__ uint32_t pack_bf16x2(float lo, float hi) {
    uint32_t u;
    asm("cvt.rn.bf16x2.f32 %0, %1, %2;" : "=r"(u) : "f"(hi), "f"(lo));
    return u;
}
__device__ __forceinline__ float fexp2nc(float t) {
    float n = rintf(t);
    float f = t - n;
    float p = 8.98934e-3f;
    p = fmaf(p, f, 5.58263e-2f);
    p = fmaf(p, f, 2.40153e-1f);
    p = fmaf(p, f, 6.93147e-1f);
    p = fmaf(p, f, 1.0f);
    return __int_as_float(__float_as_int(p) + (((int)n) << 23));
}

#define MMA_TF32(d0,d1,d2,d3,a0,a1,a2,a3,b0,b1) \
    asm volatile("mma.sync.aligned.m16n8k8.row.col.f32.tf32.tf32.f32 " \
        "{%0,%1,%2,%3}, {%4,%5,%6,%7}, {%8,%9}, {%0,%1,%2,%3};" \
        : "+f"(d0), "+f"(d1), "+f"(d2), "+f"(d3) \
        : "r"(a0), "r"(a1), "r"(a2), "r"(a3), "r"(b0), "r"(b1))

#define MMA_BF16(d0,d1,d2,d3,a0,a1,a2,a3,b0,b1) \
    asm volatile("mma.sync.aligned.m16n8k16.row.col.f32.bf16.bf16.f32 " \
        "{%0,%1,%2,%3}, {%4,%5,%6,%7}, {%8,%9}, {%0,%1,%2,%3};" \
        : "+f"(d0), "+f"(d1), "+f"(d2), "+f"(d3) \
        : "r"(a0), "r"(a1), "r"(a2), "r"(a3), "r"(b0), "r"(b1))

#define CP16(dst, src) \
    asm volatile("cp.async.cg.shared.global [%0], [%1], 16;" :: "r"(dst), "l"(src))
#define CP_COMMIT() asm volatile("cp.async.commit_group;" ::: "memory")
#define CP_WAIT1()  asm volatile("cp.async.wait_group 1;" ::: "memory")
#define CP_WAIT0()  asm volatile("cp.async.wait_group 0;" ::: "memory")

// ---------------- f32 -> bf16x2 convert ----------------
__global__ __launch_bounds__(256) void cvt_bf16(const float* __restrict__ src,
                                                uint32_t* __restrict__ dst, int n4) {
    int i = blockIdx.x * 256 + threadIdx.x;
    if (i < n4) {
        float4 v = ((const float4*)src)[i];
        ((uint2*)dst)[i] = make_uint2(pack_bf16x2(v.x, v.y), pack_bf16x2(v.z, v.w));
    }
}

// ---------------- LayerNorm: warp per row, bf16 output ----------------
__global__ __launch_bounds__(256) void ln_kernel(const float* __restrict__ x,
                                                 const float* __restrict__ w,
                                                 const float* __restrict__ b,
                                                 uint32_t* __restrict__ out) {
    int row  = blockIdx.x * 8 + (threadIdx.x >> 5);
    int lane = threadIdx.x & 31;
    const float* xr = x + (size_t)row * DMODEL;
    float4 v[6];
    float s = 0.f, ss = 0.f;
#pragma unroll
    for (int i = 0; i < 6; i++) {
        v[i] = *(const float4*)(xr + lane * 4 + i * 128);
        s  += v[i].x + v[i].y + v[i].z + v[i].w;
        ss += v[i].x * v[i].x + v[i].y * v[i].y + v[i].z * v[i].z + v[i].w * v[i].w;
    }
#pragma unroll
    for (int off = 16; off; off >>= 1) {
        s  += __shfl_xor_sync(0xffffffffu, s, off);
        ss += __shfl_xor_sync(0xffffffffu, ss, off);
    }
    float mu  = s * (1.f / DMODEL);
    float var = ss * (1.f / DMODEL) - mu * mu;
    float rstd = rsqrtf(var + 1e-6f);
    uint32_t* orow = out + (size_t)row * 384;
#pragma unroll
    for (int i = 0; i < 6; i++) {
        int c = lane * 4 + i * 128;
        float4 wv = *(const float4*)(w + c);
        float4 bv = *(const float4*)(b + c);
        float o0 = (v[i].x - mu) * rstd * wv.x + bv.x;
        float o1 = (v[i].y - mu) * rstd * wv.y + bv.y;
        float o2 = (v[i].z - mu) * rstd * wv.z + bv.z;
        float o3 = (v[i].w - mu) * rstd * wv.w + bv.w;
        *(uint2*)(orow + lane * 2 + i * 64) =
            make_uint2(pack_bf16x2(o0, o1), pack_bf16x2(o2, o3));
    }
}

// ---------------- BF16 GEMM with cp.async 3-stage pipeline ----------------
// A [M,K] bf16 (uint=bf16x2, row K/2 uints), B [N,K] bf16. BK=64 (32 uints).
// smem row stride 36 uints. 3 stages x (A 4608 + B 4608) uints = 108 KB.
// EPI 0: +bias -> f32   EPI 1: +bias,GELU -> bf16   EPI 2: res+gamma*(acc+bias) -> f32
#define SKB 36
#define STG_U (128 * SKB)
#define STAGE_U (2 * STG_U)
#define G_SMEM_BYTES (3 * STAGE_U * 4)

template <int EPI>
__global__ __launch_bounds__(256, 2)
void gemm_bf16(const uint32_t* __restrict__ A, const uint32_t* __restrict__ B,
               const float* __restrict__ bias, void* __restrict__ Cout,
               int K, int N, const float* __restrict__ res, const float* __restrict__ gamma) {
    extern __shared__ uint32_t gsm[];
    uint32_t sbase = smem_u32(gsm);

    int tid = threadIdx.x, wid = tid >> 5, lane = tid & 31;
    int g = lane >> 2, t4 = lane & 3;
    int mw = (wid & 1) * 64;
    int nw = (wid >> 1) * 32;
    int bm = blockIdx.x * 128, bn = blockIdx.y * 128;

    float acc[4][4][4];
#pragma unroll
    for (int i = 0; i < 4; i++)
#pragma unroll
        for (int j = 0; j < 4; j++)
#pragma unroll
            for (int q = 0; q < 4; q++) acc[i][j][q] = 0.f;

    int K2 = K >> 1;
    const uint32_t* Ap[4];
    const uint32_t* Bp[4];
    uint32_t sdA[4];
#pragma unroll
    for (int j = 0; j < 4; j++) {
        int fi = tid + 256 * j;
        int row = fi >> 3, ch = fi & 7;
        Ap[j] = A + (size_t)(bm + row) * K2 + ch * 4;
        Bp[j] = B + (size_t)(bn + row) * K2 + ch * 4;
        sdA[j] = (row * SKB + ch * 4) * 4;   // byte offset within stage
    }

    int NC = K >> 6;
    // prologue: stages 0,1
#pragma unroll
    for (int st = 0; st < 2; st++) {
#pragma unroll
        for (int j = 0; j < 4; j++) {
            CP16(sbase + st * (STAGE_U * 4) + sdA[j], Ap[j] + st * 32);
            CP16(sbase + st * (STAGE_U * 4) + STG_U * 4 + sdA[j], Bp[j] + st * 32);
        }
        CP_COMMIT();
    }

    for (int c = 0; c < NC; c++) {
        if (c < NC - 1) CP_WAIT1(); else CP_WAIT0();
        __syncthreads();
        if (c + 2 < NC) {
            int st = (c + 2) % 3;
#pragma unroll
            for (int j = 0; j < 4; j++) {
                CP16(sbase + st * (STAGE_U * 4) + sdA[j], Ap[j] + (c + 2) * 32);
                CP16(sbase + st * (STAGE_U * 4) + STG_U * 4 + sdA[j], Bp[j] + (c + 2) * 32);
            }
            CP_COMMIT();
        }
        const uint32_t* As = gsm + (c % 3) * STAGE_U;
        const uint32_t* Bs = As + STG_U;
#pragma unroll
        for (int s = 0; s < 4; s++) {
            int kk = t4 + 8 * s;
            uint32_t af[4][4], bf[4][2];
#pragma unroll
            for (int mt = 0; mt < 4; mt++) {
                int r0 = (mw + mt * 16 + g) * SKB;
                int r1 = r0 + 8 * SKB;
                af[mt][0] = As[r0 + kk];
                af[mt][1] = As[r1 + kk];
                af[mt][2] = As[r0 + kk + 4];
                af[mt][3] = As[r1 + kk + 4];
            }
#pragma unroll
            for (int nt = 0; nt < 4; nt++) {
                int rb = (nw + nt * 8 + g) * SKB;
                bf[nt][0] = Bs[rb + kk];
                bf[nt][1] = Bs[rb + kk + 4];
            }
#pragma unroll
            for (int mt = 0; mt < 4; mt++)
#pragma unroll
                for (int nt = 0; nt < 4; nt++)
                    MMA_BF16(acc[mt][nt][0], acc[mt][nt][1], acc[mt][nt][2], acc[mt][nt][3],
                             af[mt][0], af[mt][1], af[mt][2], af[mt][3], bf[nt][0], bf[nt][1]);
        }
    }

#pragma unroll
    for (int mt = 0; mt < 4; mt++) {
#pragma unroll
        for (int half = 0; half < 2; half++) {
            int r = bm + mw + mt * 16 + g + half * 8;
            const float* resr = (EPI == 2) ? res + (size_t)r * N : nullptr;
#pragma unroll
            for (int nt = 0; nt < 4; nt++) {
                int cn = bn + nw + nt * 8 + 2 * t4;
                float v0 = acc[mt][nt][half * 2 + 0] + bias[cn];
                float v1 = acc[mt][nt][half * 2 + 1] + bias[cn + 1];
                if (EPI == 1) {
                    v0 = 0.5f * v0 * (1.f + erff(v0 * 0.70710678118654752f));
                    v1 = 0.5f * v1 * (1.f + erff(v1 * 0.70710678118654752f));
                    ((uint32_t*)Cout)[(size_t)r * (N >> 1) + (cn >> 1)] = pack_bf16x2(v0, v1);
                } else if (EPI == 2) {
                    v0 = resr[cn] + gamma[cn] * v0;
                    v1 = resr[cn + 1] + gamma[cn + 1] * v1;
                    *(float2*)((float*)Cout + (size_t)r * N + cn) = make_float2(v0, v1);
                } else {
                    *(float2*)((float*)Cout + (size_t)r * N + cn) = make_float2(v0, v1);
                }
            }
        }
    }
}

// ---------------- Flash attention (tf32, bf16 output) ----------------
#define KVROW 68
#define KVBUF (128 * KVROW)
#define A_SMEM2 (2 * KVBUF * 4)

__global__ __launch_bounds__(256) void attn_mma2(const float* __restrict__ qkv,
                                                 uint32_t* __restrict__ outb) {
    extern __shared__ uint32_t sm[];

    int bx = blockIdx.x, h = blockIdx.y;
    int s = 0;
#pragma unroll
    for (int i = 1; i < 8; i++) s += (bx >= c_pfx128[i]) ? 1 : 0;
    int q0   = (bx - c_pfx128[s]) * 128;
    int base = c_cu[s];
    int L    = c_cu[s + 1] - base;

    int tid = threadIdx.x, wid = tid >> 5, lane = tid & 31;
    int g = lane >> 2, t4 = lane & 3;
    int ltok = tid >> 2;
    int dg   = (tid & 3) << 4;

    const float QSC = 0.18033688011112042f;
    uint32_t qa[8][4];
    {
        int r0 = q0 + wid * 16 + g, r1 = r0 + 8;
        bool v0 = r0 < L, v1 = r1 < L;
        const float* p0 = qkv + (size_t)(base + (v0 ? r0 : 0)) * 2304 + h * 64;
        const float* p1 = qkv + (size_t)(base + (v1 ? r1 : 0)) * 2304 + h * 64;
#pragma unroll
        for (int s8 = 0; s8 < 8; s8++) {
            int k0 = t4 + 8 * s8, k1 = k0 + 4;
            qa[s8][0] = v0 ? f2tf32(p0[k0] * QSC) : 0u;
            qa[s8][1] = v1 ? f2tf32(p1[k0] * QSC) : 0u;
            qa[s8][2] = v0 ? f2tf32(p0[k1] * QSC) : 0u;
            qa[s8][3] = v1 ? f2tf32(p1[k1] * QSC) : 0u;
        }
    }

    float l0 = 0.f, l1 = 0.f;
    float acco[8][4];
#pragma unroll
    for (int nt = 0; nt < 8; nt++)
#pragma unroll
        for (int q = 0; q < 4; q++) acco[nt][q] = 0.f;

    int nkt = (L + 63) >> 6;

    float4 kr[4], vr[4];
    bool kvalid;
    {
        int r = ltok;
        kvalid = r < L;
        const float* kp = qkv + (size_t)(base + (kvalid ? r : 0)) * 2304 + 768 + h * 64 + dg;
#pragma unroll
        for (int j = 0; j < 4; j++) {
            kr[j] = kvalid ? *(const float4*)(kp + j * 4) : make_float4(0, 0, 0, 0);
            vr[j] = kvalid ? *(const float4*)(kp + 768 + j * 4) : make_float4(0, 0, 0, 0);
        }
    }
    {
        uint32_t* Kb = sm;
        uint32_t* Vb = sm + 64 * KVROW;
        uint32_t kbase = ltok * KVROW + (dg >> 2);
#pragma unroll
        for (int c = 0; c < 4; c++) {
            float x0 = (&kr[0].x)[c], x1 = (&kr[1].x)[c], x2 = (&kr[2].x)[c], x3 = (&kr[3].x)[c];
            *(uint4*)&Kb[kbase + c * 16] = make_uint4(f2tf32(x0), f2tf32(x1), f2tf32(x2), f2tf32(x3));
        }
#pragma unroll
        for (int j = 0; j < 4; j++)
#pragma unroll
            for (int c = 0; c < 4; c++) {
                int idx = (4 * (j & 1) + c) * 8 + (dg >> 3) + (j >> 1);
                Vb[ltok * KVROW + idx] = f2tf32((&vr[j].x)[c]);
            }
    }

    for (int kt = 0; kt < nkt; kt++) {
        int kb = kt << 6;
        if (kt + 1 < nkt) {
            int r = kb + 64 + ltok;
            kvalid = r < L;
            const float* kp = qkv + (size_t)(base + (kvalid ? r : 0)) * 2304 + 768 + h * 64 + dg;
#pragma unroll
            for (int j = 0; j < 4; j++) {
                kr[j] = kvalid ? *(const float4*)(kp + j * 4) : make_float4(0, 0, 0, 0);
                vr[j] = kvalid ? *(const float4*)(kp + 768 + j * 4) : make_float4(0, 0, 0, 0);
            }
        }
        __syncthreads();

        uint32_t* Kb = sm + (kt & 1) * KVBUF;
        uint32_t* Vb = Kb + 64 * KVROW;

        float sc[8][4];
#pragma unroll
        for (int nt = 0; nt < 8; nt++) {
            sc[nt][0] = 0.f; sc[nt][1] = 0.f; sc[nt][2] = 0.f; sc[nt][3] = 0.f;
            const uint32_t* kp = &Kb[(nt * 8 + g) * KVROW + t4 * 16];
            uint4 k0 = *(const uint4*)(kp);
            uint4 k1 = *(const uint4*)(kp + 4);
            uint4 k2 = *(const uint4*)(kp + 8);
            uint4 k3 = *(const uint4*)(kp + 12);
            uint32_t kk[16] = {k0.x, k0.y, k0.z, k0.w, k1.x, k1.y, k1.z, k1.w,
                               k2.x, k2.y, k2.z, k2.w, k3.x, k3.y, k3.z, k3.w};
#pragma unroll
            for (int s8 = 0; s8 < 8; s8++)
                MMA_TF32(sc[nt][0], sc[nt][1], sc[nt][2], sc[nt][3],
                         qa[s8][0], qa[s8][1], qa[s8][2], qa[s8][3], kk[2 * s8], kk[2 * s8 + 1]);
        }

        if (kt + 1 < nkt) {
            uint32_t* Kn = sm + ((kt + 1) & 1) * KVBUF;
            uint32_t* Vn = Kn + 64 * KVROW;
            uint32_t kbase = ltok * KVROW + (dg >> 2);
#pragma unroll
            for (int c = 0; c < 4; c++) {
                float x0 = (&kr[0].x)[c], x1 = (&kr[1].x)[c], x2 = (&kr[2].x)[c], x3 = (&kr[3].x)[c];
                *(uint4*)&Kn[kbase + c * 16] = make_uint4(f2tf32(x0), f2tf32(x1), f2tf32(x2), f2tf32(x3));
            }
#pragma unroll
            for (int j = 0; j < 4; j++)
#pragma unroll
                for (int c = 0; c < 4; c++) {
                    int idx = (4 * (j & 1) + c) * 8 + (dg >> 3) + (j >> 1);
                    Vn[ltok * KVROW + idx] = f2tf32((&vr[j].x)[c]);
                }
        }

        if (kb + 64 > L) {
#pragma unroll
            for (int nt = 0; nt < 8; nt++) {
                int col = kb + nt * 8 + 2 * t4;
                if (col >= L)     { sc[nt][0] = -126.f; sc[nt][2] = -126.f; }
                if (col + 1 >= L) { sc[nt][1] = -126.f; sc[nt][3] = -126.f; }
            }
        }
#pragma unroll
        for (int nt = 0; nt < 8; nt++) {
            float p0 = fexp2nc(sc[nt][0]);
            float p1 = fexp2nc(sc[nt][1]);
            float p2 = fexp2nc(sc[nt][2]);
            float p3 = fexp2nc(sc[nt][3]);
            l0 += p0 + p1; l1 += p2 + p3;
            sc[nt][0] = p0; sc[nt][1] = p1; sc[nt][2] = p2; sc[nt][3] = p3;
        }

        int srcA = (lane & 28) | (t4 >> 1);
        bool odd = (t4 & 1);
#pragma unroll
        for (int s8 = 0; s8 < 8; s8++) {
            float u0 = __shfl_sync(0xffffffffu, sc[s8][0], srcA);
            float u1 = __shfl_sync(0xffffffffu, sc[s8][1], srcA);
            float u2 = __shfl_sync(0xffffffffu, sc[s8][2], srcA);
            float u3 = __shfl_sync(0xffffffffu, sc[s8][3], srcA);
            float w0 = __shfl_sync(0xffffffffu, sc[s8][0], srcA + 2);
            float w1 = __shfl_sync(0xffffffffu, sc[s8][1], srcA + 2);
            float w2 = __shfl_sync(0xffffffffu, sc[s8][2], srcA + 2);
            float w3 = __shfl_sync(0xffffffffu, sc[s8][3], srcA + 2);
            uint32_t pa0 = __float_as_uint(odd ? u1 : u0);
            uint32_t pa1 = __float_as_uint(odd ? u3 : u2);
            uint32_t pa2 = __float_as_uint(odd ? w1 : w0);
            uint32_t pa3 = __float_as_uint(odd ? w3 : w2);
            const uint32_t* v1p = &Vb[(t4 + 8 * s8) * KVROW + g * 8];
            const uint32_t* v2p = &Vb[(t4 + 4 + 8 * s8) * KVROW + g * 8];
            uint4 va = *(const uint4*)(v1p);
            uint4 vb2 = *(const uint4*)(v1p + 4);
            uint4 vc = *(const uint4*)(v2p);
            uint4 vd = *(const uint4*)(v2p + 4);
            uint32_t b0a[8] = {va.x, va.y, va.z, va.w, vb2.x, vb2.y, vb2.z, vb2.w};
            uint32_t b1a[8] = {vc.x, vc.y, vc.z, vc.w, vd.x, vd.y, vd.z, vd.w};
#pragma unroll
            for (int nt = 0; nt < 8; nt++)
                MMA_TF32(acco[nt][0], acco[nt][1], acco[nt][2], acco[nt][3],
                         pa0, pa1, pa2, pa3, b0a[nt], b1a[nt]);
        }
    }

#pragma unroll
    for (int off = 1; off <= 2; off <<= 1) {
        l0 += __shfl_xor_sync(0xffffffffu, l0, off);
        l1 += __shfl_xor_sync(0xffffffffu, l1, off);
    }
    float inv0 = 1.f / l0, inv1 = 1.f / l1;
    int r0 = q0 + wid * 16 + g, r1 = r0 + 8;
#pragma unroll
    for (int nt = 0; nt < 8; nt++) {
        int col = h * 64 + nt * 8 + 2 * t4;
        if (r0 < L)
            outb[(size_t)(base + r0) * 384 + (col >> 1)] =
                pack_bf16x2(acco[nt][0] * inv0, acco[nt][1] * inv0);
        if (r1 < L)
            outb[(size_t)(base + r1) * 384 + (col >> 1)] =
                pack_bf16x2(acco[nt][2] * inv1, acco[nt][3] * inv1);
    }
}

// ---------------- launch ----------------
extern "C" void kernel_launch(void* const* d_in, const int* in_sizes, int n_in,
                              void* d_out, int out_size) {
    const float* x      = (const float*)d_in[0];
    const float* n1w    = (const float*)d_in[1];
    const float* n1b    = (const float*)d_in[2];
    const float* qkv_w  = (const float*)d_in[3];
    const float* qkv_b  = (const float*)d_in[4];
    const float* proj_w = (const float*)d_in[5];
    const float* proj_b = (const float*)d_in[6];
    const float* ls1    = (const float*)d_in[7];
    const float* n2w    = (const float*)d_in[8];
    const float* n2b    = (const float*)d_in[9];
    const float* fc1_w  = (const float*)d_in[10];
    const float* fc1_b  = (const float*)d_in[11];
    const float* fc2_w  = (const float*)d_in[12];
    const float* fc2_b  = (const float*)d_in[13];
    const float* ls2    = (const float*)d_in[14];
    float* out = (float*)d_out;

    uint32_t *xnb, *attnb, *hb, *wq, *wp, *w1, *w2;
    float *qkvf, *x1;
    cudaGetSymbolAddress((void**)&xnb,   g_xnb);
    cudaGetSymbolAddress((void**)&qkvf,  g_qkv);
    cudaGetSymbolAddress((void**)&attnb, g_attnb);
    cudaGetSymbolAddress((void**)&x1,    g_x1);
    cudaGetSymbolAddress((void**)&hb,    g_hb);
    cudaGetSymbolAddress((void**)&wq,    g_wq);
    cudaGetSymbolAddress((void**)&wp,    g_wp);
    cudaGetSymbolAddress((void**)&w1,    g_w1);
    cudaGetSymbolAddress((void**)&w2,    g_w2);

    cudaFuncSetAttribute(attn_mma2, cudaFuncAttributeMaxDynamicSharedMemorySize, A_SMEM2);
    cudaFuncSetAttribute(gemm_bf16<0>, cudaFuncAttributeMaxDynamicSharedMemorySize, G_SMEM_BYTES);
    cudaFuncSetAttribute(gemm_bf16<1>, cudaFuncAttributeMaxDynamicSharedMemorySize, G_SMEM_BYTES);
    cudaFuncSetAttribute(gemm_bf16<2>, cudaFuncAttributeMaxDynamicSharedMemorySize, G_SMEM_BYTES);

    cvt_bf16<<<1728, 256>>>(qkv_w, wq, 442368);
    cvt_bf16<<<576, 256>>>(proj_w, wp, 147456);
    ln_kernel<<<576, 256>>>(x, n1w, n1b, xnb);
    gemm_bf16<0><<<dim3(36, 18), 256, G_SMEM_BYTES>>>(xnb, wq, qkv_b, qkvf, 768, 2304, nullptr, nullptr);
    attn_mma2<<<dim3(37, 12), 256, A_SMEM2>>>(qkvf, attnb);
    gemm_bf16<2><<<dim3(36, 6), 256, G_SMEM_BYTES>>>(attnb, wp, proj_b, x1, 768, 768, x, ls1);
    cvt_bf16<<<2304, 256>>>(fc1_w, w1, 589824);
    cvt_bf16<<<2304, 256>>>(fc2_w, w2, 589824);
    ln_kernel<<<576, 256>>>(x1, n2w, n2b, xnb);
    gemm_bf16<1><<<dim3(36, 24), 256, G_SMEM_BYTES>>>(xnb, w1, fc1_b, hb, 768, 3072, nullptr, nullptr);
    gemm_bf16<2><<<dim3(36, 6), 256, G_SMEM_BYTES>>>(hb, w2, fc2_b, out, 3072, 768, x1, ls2);
}

// round 13
// speedup vs baseline: 2.1104x; 1.1553x over previous
#include <cuda_runtime.h>
#include <math.h>
#include <cstdint>

#define TOTAL 4608
#define DMODEL 768
#define DFF 3072

// -------- scratch --------
__device__ uint32_t g_xnb  [TOTAL * 384];    // bf16x2 LN output
__device__ float    g_qkv  [TOTAL * 2304];   // f32 qkv (attention input)
__device__ uint32_t g_attnb[TOTAL * 384];    // bf16x2 attention output
__device__ float    g_x1   [TOTAL * 768];
__device__ uint32_t g_hb   [TOTAL * 1536];   // bf16x2 GELU output
__device__ uint32_t g_wq   [884736];
__device__ uint32_t g_wp   [294912];
__device__ uint32_t g_w1   [1179648];
__device__ uint32_t g_w2   [1179648];

__constant__ int c_cu[9]     = {0, 1024, 1920, 2688, 3328, 3840, 4288, 4544, 4608};
__constant__ int c_pfx128[9] = {0, 8, 15, 21, 26, 30, 34, 36, 37};

__device__ __forceinline__ uint32_t smem_u32(const void* p) {
    uint32_t a;
    asm("{ .reg .u64 t; cvta.to.shared.u64 t, %1; cvt.u32.u64 %0, t; }" : "=r"(a) : "l"(p));
    return a;
}
__device__ __forceinline__ uint32_t pack_bf16x2(float lo, float hi) {
    uint32_t u;
    asm("cvt.rn.bf16x2.f32 %0, %1, %2;" : "=r"(u) : "f"(hi), "f"(lo));
    return u;
}
__device__ __forceinline__ uint16_t f2bf16(float v) {
    uint16_t h;
    asm("cvt.rn.bf16.f32 %0, %1;" : "=h"(h) : "f"(v));
    return h;
}
__device__ __forceinline__ float fexp2nc(float t) {
    float n = rintf(t);
    float f = t - n;
    float p = 8.98934e-3f;
    p = fmaf(p, f, 5.58263e-2f);
    p = fmaf(p, f, 2.40153e-1f);
    p = fmaf(p, f, 6.93147e-1f);
    p = fmaf(p, f, 1.0f);
    return __int_as_float(__float_as_int(p) + (((int)n) << 23));
}

#define MMA_BF16(d0,d1,d2,d3,a0,a1,a2,a3,b0,b1) \
    asm volatile("mma.sync.aligned.m16n8k16.row.col.f32.bf16.bf16.f32 " \
        "{%0,%1,%2,%3}, {%4,%5,%6,%7}, {%8,%9}, {%0,%1,%2,%3};" \
        : "+f"(d0), "+f"(d1), "+f"(d2), "+f"(d3) \
        : "r"(a0), "r"(a1), "r"(a2), "r"(a3), "r"(b0), "r"(b1))

#define CP16(dst, src) \
    asm volatile("cp.async.cg.shared.global [%0], [%1], 16;" :: "r"(dst), "l"(src))
#define CP_COMMIT() asm volatile("cp.async.commit_group;" ::: "memory")
#define CP_WAIT1()  asm volatile("cp.async.wait_group 1;" ::: "memory")
#define CP_WAIT0()  asm volatile("cp.async.wait_group 0;" ::: "memory")

// ---------------- f32 -> bf16x2 convert ----------------
__global__ __launch_bounds__(256) void cvt_bf16(const float* __restrict__ src,
                                                uint32_t* __restrict__ dst, int n4) {
    int i = blockIdx.x * 256 + threadIdx.x;
    if (i < n4) {
        float4 v = ((const float4*)src)[i];
        ((uint2*)dst)[i] = make_uint2(pack_bf16x2(v.x, v.y), pack_bf16x2(v.z, v.w));
    }
}

// ---------------- LayerNorm: warp per row, bf16 output ----------------
__global__ __launch_bounds__(256) void ln_kernel(const float* __restrict__ x,
                                                 const float* __restrict__ w,
                                                 const float* __restrict__ b,
                                                 uint32_t* __restrict__ out) {
    int row  = blockIdx.x * 8 + (threadIdx.x >> 5);
    int lane = threadIdx.x & 31;
    const float* xr = x + (size_t)row * DMODEL;
    float4 v[6];
    float s = 0.f, ss = 0.f;
#pragma unroll
    for (int i = 0; i < 6; i++) {
        v[i] = *(const float4*)(xr + lane * 4 + i * 128);
        s  += v[i].x + v[i].y + v[i].z + v[i].w;
        ss += v[i].x * v[i].x + v[i].y * v[i].y + v[i].z * v[i].z + v[i].w * v[i].w;
    }
#pragma unroll
    for (int off = 16; off; off >>= 1) {
        s  += __shfl_xor_sync(0xffffffffu, s, off);
        ss += __shfl_xor_sync(0xffffffffu, ss, off);
    }
    float mu  = s * (1.f / DMODEL);
    float var = ss * (1.f / DMODEL) - mu * mu;
    float rstd = rsqrtf(var + 1e-6f);
    uint32_t* orow = out + (size_t)row * 384;
#pragma unroll
    for (int i = 0; i < 6; i++) {
        int c = lane * 4 + i * 128;
        float4 wv = *(const float4*)(w + c);
        float4 bv = *(const float4*)(b + c);
        float o0 = (v[i].x - mu) * rstd * wv.x + bv.x;
        float o1 = (v[i].y - mu) * rstd * wv.y + bv.y;
        float o2 = (v[i].z - mu) * rstd * wv.z + bv.z;
        float o3 = (v[i].w - mu) * rstd * wv.w + bv.w;
        *(uint2*)(orow + lane * 2 + i * 64) =
            make_uint2(pack_bf16x2(o0, o1), pack_bf16x2(o2, o3));
    }
}

// ---------------- BF16 GEMM with cp.async 3-stage pipeline (unchanged R12) ----
#define SKB 36
#define STG_U (128 * SKB)
#define STAGE_U (2 * STG_U)
#define G_SMEM_BYTES (3 * STAGE_U * 4)

template <int EPI>
__global__ __launch_bounds__(256, 2)
void gemm_bf16(const uint32_t* __restrict__ A, const uint32_t* __restrict__ B,
               const float* __restrict__ bias, void* __restrict__ Cout,
               int K, int N, const float* __restrict__ res, const float* __restrict__ gamma) {
    extern __shared__ uint32_t gsm[];
    uint32_t sbase = smem_u32(gsm);

    int tid = threadIdx.x, wid = tid >> 5, lane = tid & 31;
    int g = lane >> 2, t4 = lane & 3;
    int mw = (wid & 1) * 64;
    int nw = (wid >> 1) * 32;
    int bm = blockIdx.x * 128, bn = blockIdx.y * 128;

    float acc[4][4][4];
#pragma unroll
    for (int i = 0; i < 4; i++)
#pragma unroll
        for (int j = 0; j < 4; j++)
#pragma unroll
            for (int q = 0; q < 4; q++) acc[i][j][q] = 0.f;

    int K2 = K >> 1;
    const uint32_t* Ap[4];
    const uint32_t* Bp[4];
    uint32_t sdA[4];
#pragma unroll
    for (int j = 0; j < 4; j++) {
        int fi = tid + 256 * j;
        int row = fi >> 3, ch = fi & 7;
        Ap[j] = A + (size_t)(bm + row) * K2 + ch * 4;
        Bp[j] = B + (size_t)(bn + row) * K2 + ch * 4;
        sdA[j] = (row * SKB + ch * 4) * 4;
    }

    int NC = K >> 6;
#pragma unroll
    for (int st = 0; st < 2; st++) {
#pragma unroll
        for (int j = 0; j < 4; j++) {
            CP16(sbase + st * (STAGE_U * 4) + sdA[j], Ap[j] + st * 32);
            CP16(sbase + st * (STAGE_U * 4) + STG_U * 4 + sdA[j], Bp[j] + st * 32);
        }
        CP_COMMIT();
    }

    for (int c = 0; c < NC; c++) {
        if (c < NC - 1) CP_WAIT1(); else CP_WAIT0();
        __syncthreads();
        if (c + 2 < NC) {
            int st = (c + 2) % 3;
#pragma unroll
            for (int j = 0; j < 4; j++) {
                CP16(sbase + st * (STAGE_U * 4) + sdA[j], Ap[j] + (c + 2) * 32);
                CP16(sbase + st * (STAGE_U * 4) + STG_U * 4 + sdA[j], Bp[j] + (c + 2) * 32);
            }
            CP_COMMIT();
        }
        const uint32_t* As = gsm + (c % 3) * STAGE_U;
        const uint32_t* Bs = As + STG_U;
#pragma unroll
        for (int s = 0; s < 4; s++) {
            int kk = t4 + 8 * s;
            uint32_t af[4][4], bf[4][2];
#pragma unroll
            for (int mt = 0; mt < 4; mt++) {
                int r0 = (mw + mt * 16 + g) * SKB;
                int r1 = r0 + 8 * SKB;
                af[mt][0] = As[r0 + kk];
                af[mt][1] = As[r1 + kk];
                af[mt][2] = As[r0 + kk + 4];
                af[mt][3] = As[r1 + kk + 4];
            }
#pragma unroll
            for (int nt = 0; nt < 4; nt++) {
                int rb = (nw + nt * 8 + g) * SKB;
                bf[nt][0] = Bs[rb + kk];
                bf[nt][1] = Bs[rb + kk + 4];
            }
#pragma unroll
            for (int mt = 0; mt < 4; mt++)
#pragma unroll
                for (int nt = 0; nt < 4; nt++)
                    MMA_BF16(acc[mt][nt][0], acc[mt][nt][1], acc[mt][nt][2], acc[mt][nt][3],
                             af[mt][0], af[mt][1], af[mt][2], af[mt][3], bf[nt][0], bf[nt][1]);
        }
    }

#pragma unroll
    for (int mt = 0; mt < 4; mt++) {
#pragma unroll
        for (int half = 0; half < 2; half++) {
            int r = bm + mw + mt * 16 + g + half * 8;
            const float* resr = (EPI == 2) ? res + (size_t)r * N : nullptr;
#pragma unroll
            for (int nt = 0; nt < 4; nt++) {
                int cn = bn + nw + nt * 8 + 2 * t4;
                float v0 = acc[mt][nt][half * 2 + 0] + bias[cn];
                float v1 = acc[mt][nt][half * 2 + 1] + bias[cn + 1];
                if (EPI == 1) {
                    v0 = 0.5f * v0 * (1.f + erff(v0 * 0.70710678118654752f));
                    v1 = 0.5f * v1 * (1.f + erff(v1 * 0.70710678118654752f));
                    ((uint32_t*)Cout)[(size_t)r * (N >> 1) + (cn >> 1)] = pack_bf16x2(v0, v1);
                } else if (EPI == 2) {
                    v0 = resr[cn] + gamma[cn] * v0;
                    v1 = resr[cn + 1] + gamma[cn + 1] * v1;
                    *(float2*)((float*)Cout + (size_t)r * N + cn) = make_float2(v0, v1);
                } else {
                    *(float2*)((float*)Cout + (size_t)r * N + cn) = make_float2(v0, v1);
                }
            }
        }
    }
}

// ---------------- Flash attention v4: all-bf16, zero-shuffle P forwarding ----
// K tile: 64 rows x 32 uints (bf16x2 of d pairs), stride 36.
// V tile: transposed, row d (64), 32 uints (token pairs), row offset d*36+(d>>4)*8.
#define KST 36
#define VOFF (64 * KST)
#define ABUF (VOFF + 64 * KST + 32)
__device__ __forceinline__ int vrow(int d) { return d * KST + ((d >> 4) << 3); }

__global__ __launch_bounds__(256) void attn_mma2(const float* __restrict__ qkv,
                                                 uint32_t* __restrict__ outb) {
    __shared__ uint32_t sm[2 * ABUF];

    int bx = blockIdx.x, h = blockIdx.y;
    int s = 0;
#pragma unroll
    for (int i = 1; i < 8; i++) s += (bx >= c_pfx128[i]) ? 1 : 0;
    int q0   = (bx - c_pfx128[s]) * 128;
    int base = c_cu[s];
    int L    = c_cu[s + 1] - base;

    int tid = threadIdx.x, wid = tid >> 5, lane = tid & 31;
    int g = lane >> 2, t4 = lane & 3;
    int ltok = tid >> 2;
    int dg   = (tid & 3) << 4;

    // ---- preload Q fragments (bf16, scaled by log2e/8) ----
    const float QSC = 0.18033688011112042f;
    uint32_t qa[4][4];
    {
        int r0 = q0 + wid * 16 + g, r1 = r0 + 8;
        bool v0 = r0 < L, v1 = r1 < L;
        const float* p0 = qkv + (size_t)(base + (v0 ? r0 : 0)) * 2304 + h * 64;
        const float* p1 = qkv + (size_t)(base + (v1 ? r1 : 0)) * 2304 + h * 64;
#pragma unroll
        for (int st = 0; st < 4; st++) {
            int k0 = 16 * st + 2 * t4, k1 = k0 + 8;
            qa[st][0] = v0 ? pack_bf16x2(p0[k0] * QSC, p0[k0 + 1] * QSC) : 0u;
            qa[st][1] = v1 ? pack_bf16x2(p1[k0] * QSC, p1[k0 + 1] * QSC) : 0u;
            qa[st][2] = v0 ? pack_bf16x2(p0[k1] * QSC, p0[k1 + 1] * QSC) : 0u;
            qa[st][3] = v1 ? pack_bf16x2(p1[k1] * QSC, p1[k1 + 1] * QSC) : 0u;
        }
    }

    float l0 = 0.f, l1 = 0.f;
    float acco[8][4];
#pragma unroll
    for (int nt = 0; nt < 8; nt++)
#pragma unroll
        for (int q = 0; q < 4; q++) acco[nt][q] = 0.f;

    int nkt = (L + 63) >> 6;

    float4 kr[4], vr[4];
    bool kvalid;
    {
        int r = ltok;
        kvalid = r < L;
        const float* kp = qkv + (size_t)(base + (kvalid ? r : 0)) * 2304 + 768 + h * 64 + dg;
#pragma unroll
        for (int j = 0; j < 4; j++) {
            kr[j] = kvalid ? *(const float4*)(kp + j * 4) : make_float4(0, 0, 0, 0);
            vr[j] = kvalid ? *(const float4*)(kp + 768 + j * 4) : make_float4(0, 0, 0, 0);
        }
    }
    {
        uint32_t* Kb = sm;
        uint32_t kb2 = ltok * KST + (dg >> 1);
        *(uint4*)&Kb[kb2] = make_uint4(pack_bf16x2(kr[0].x, kr[0].y), pack_bf16x2(kr[0].z, kr[0].w),
                                       pack_bf16x2(kr[1].x, kr[1].y), pack_bf16x2(kr[1].z, kr[1].w));
        *(uint4*)&Kb[kb2 + 4] = make_uint4(pack_bf16x2(kr[2].x, kr[2].y), pack_bf16x2(kr[2].z, kr[2].w),
                                           pack_bf16x2(kr[3].x, kr[3].y), pack_bf16x2(kr[3].z, kr[3].w));
        uint16_t* Vh = (uint16_t*)(Kb + VOFF);
#pragma unroll
        for (int j = 0; j < 4; j++)
#pragma unroll
            for (int c = 0; c < 4; c++)
                Vh[vrow(dg + 4 * j + c) * 2 + ltok] = f2bf16((&vr[j].x)[c]);
    }

    for (int kt = 0; kt < nkt; kt++) {
        int kb = kt << 6;
        if (kt + 1 < nkt) {
            int r = kb + 64 + ltok;
            kvalid = r < L;
            const float* kp = qkv + (size_t)(base + (kvalid ? r : 0)) * 2304 + 768 + h * 64 + dg;
#pragma unroll
            for (int j = 0; j < 4; j++) {
                kr[j] = kvalid ? *(const float4*)(kp + j * 4) : make_float4(0, 0, 0, 0);
                vr[j] = kvalid ? *(const float4*)(kp + 768 + j * 4) : make_float4(0, 0, 0, 0);
            }
        }
        __syncthreads();

        const uint32_t* Kb = sm + (kt & 1) * ABUF;
        const uint32_t* Vb = Kb + VOFF;

        // ---- S = Q K^T (bf16, log2 domain) ----
        float sc[8][4];
#pragma unroll
        for (int nt = 0; nt < 8; nt++) {
            sc[nt][0] = 0.f; sc[nt][1] = 0.f; sc[nt][2] = 0.f; sc[nt][3] = 0.f;
        }
#pragma unroll
        for (int st = 0; st < 4; st++) {
            int kk = t4 + 8 * st;
#pragma unroll
            for (int nt = 0; nt < 8; nt++) {
                int rb = (nt * 8 + g) * KST;
                MMA_BF16(sc[nt][0], sc[nt][1], sc[nt][2], sc[nt][3],
                         qa[st][0], qa[st][1], qa[st][2], qa[st][3],
                         Kb[rb + kk], Kb[rb + kk + 4]);
            }
        }

        // ---- STS next tile (overlaps softmax) ----
        if (kt + 1 < nkt) {
            uint32_t* Kn = sm + ((kt + 1) & 1) * ABUF;
            uint32_t kb2 = ltok * KST + (dg >> 1);
            *(uint4*)&Kn[kb2] = make_uint4(pack_bf16x2(kr[0].x, kr[0].y), pack_bf16x2(kr[0].z, kr[0].w),
                                           pack_bf16x2(kr[1].x, kr[1].y), pack_bf16x2(kr[1].z, kr[1].w));
            *(uint4*)&Kn[kb2 + 4] = make_uint4(pack_bf16x2(kr[2].x, kr[2].y), pack_bf16x2(kr[2].z, kr[2].w),
                                               pack_bf16x2(kr[3].x, kr[3].y), pack_bf16x2(kr[3].z, kr[3].w));
            uint16_t* Vh = (uint16_t*)(Kn + VOFF);
#pragma unroll
            for (int j = 0; j < 4; j++)
#pragma unroll
                for (int c = 0; c < 4; c++)
                    Vh[vrow(dg + 4 * j + c) * 2 + ltok] = f2bf16((&vr[j].x)[c]);
        }

        // ---- mask + fixed-max softmax (exp2 domain) ----
        if (kb + 64 > L) {
#pragma unroll
            for (int nt = 0; nt < 8; nt++) {
                int col = kb + nt * 8 + 2 * t4;
                if (col >= L)     { sc[nt][0] = -126.f; sc[nt][2] = -126.f; }
                if (col + 1 >= L) { sc[nt][1] = -126.f; sc[nt][3] = -126.f; }
            }
        }
#pragma unroll
        for (int nt = 0; nt < 8; nt++) {
            float p0 = fexp2nc(sc[nt][0]);
            float p1 = fexp2nc(sc[nt][1]);
            float p2 = fexp2nc(sc[nt][2]);
            float p3 = fexp2nc(sc[nt][3]);
            l0 += p0 + p1; l1 += p2 + p3;
            sc[nt][0] = p0; sc[nt][1] = p1; sc[nt][2] = p2; sc[nt][3] = p3;
        }

        // ---- O += P V : P packs directly from accumulator layout ----
#pragma unroll
        for (int st = 0; st < 4; st++) {
            uint32_t pa0 = pack_bf16x2(sc[2 * st][0], sc[2 * st][1]);
            uint32_t pa1 = pack_bf16x2(sc[2 * st][2], sc[2 * st][3]);
            uint32_t pa2 = pack_bf16x2(sc[2 * st + 1][0], sc[2 * st + 1][1]);
            uint32_t pa3 = pack_bf16x2(sc[2 * st + 1][2], sc[2 * st + 1][3]);
            int kk = 8 * st + t4;
#pragma unroll
            for (int nt = 0; nt < 8; nt++) {
                int rb = vrow(nt * 8 + g);
                MMA_BF16(acco[nt][0], acco[nt][1], acco[nt][2], acco[nt][3],
                         pa0, pa1, pa2, pa3, Vb[rb + kk], Vb[rb + kk + 4]);
            }
        }
    }

    // ---- final row-sum reduction + write O (bf16) ----
#pragma unroll
    for (int off = 1; off <= 2; off <<= 1) {
        l0 += __shfl_xor_sync(0xffffffffu, l0, off);
        l1 += __shfl_xor_sync(0xffffffffu, l1, off);
    }
    float inv0 = 1.f / l0, inv1 = 1.f / l1;
    int r0 = q0 + wid * 16 + g, r1 = r0 + 8;
#pragma unroll
    for (int nt = 0; nt < 8; nt++) {
        int col = h * 64 + nt * 8 + 2 * t4;
        if (r0 < L)
            outb[(size_t)(base + r0) * 384 + (col >> 1)] =
                pack_bf16x2(acco[nt][0] * inv0, acco[nt][1] * inv0);
        if (r1 < L)
            outb[(size_t)(base + r1) * 384 + (col >> 1)] =
                pack_bf16x2(acco[nt][2] * inv1, acco[nt][3] * inv1);
    }
}

// ---------------- launch ----------------
extern "C" void kernel_launch(void* const* d_in, const int* in_sizes, int n_in,
                              void* d_out, int out_size) {
    const float* x      = (const float*)d_in[0];
    const float* n1w    = (const float*)d_in[1];
    const float* n1b    = (const float*)d_in[2];
    const float* qkv_w  = (const float*)d_in[3];
    const float* qkv_b  = (const float*)d_in[4];
    const float* proj_w = (const float*)d_in[5];
    const float* proj_b = (const float*)d_in[6];
    const float* ls1    = (const float*)d_in[7];
    const float* n2w    = (const float*)d_in[8];
    const float* n2b    = (const float*)d_in[9];
    const float* fc1_w  = (const float*)d_in[10];
    const float* fc1_b  = (const float*)d_in[11];
    const float* fc2_w  = (const float*)d_in[12];
    const float* fc2_b  = (const float*)d_in[13];
    const float* ls2    = (const float*)d_in[14];
    float* out = (float*)d_out;

    uint32_t *xnb, *attnb, *hb, *wq, *wp, *w1, *w2;
    float *qkvf, *x1;
    cudaGetSymbolAddress((void**)&xnb,   g_xnb);
    cudaGetSymbolAddress((void**)&qkvf,  g_qkv);
    cudaGetSymbolAddress((void**)&attnb, g_attnb);
    cudaGetSymbolAddress((void**)&x1,    g_x1);
    cudaGetSymbolAddress((void**)&hb,    g_hb);
    cudaGetSymbolAddress((void**)&wq,    g_wq);
    cudaGetSymbolAddress((void**)&wp,    g_wp);
    cudaGetSymbolAddress((void**)&w1,    g_w1);
    cudaGetSymbolAddress((void**)&w2,    g_w2);

    cudaFuncSetAttribute(gemm_bf16<0>, cudaFuncAttributeMaxDynamicSharedMemorySize, G_SMEM_BYTES);
    cudaFuncSetAttribute(gemm_bf16<1>, cudaFuncAttributeMaxDynamicSharedMemorySize, G_SMEM_BYTES);
    cudaFuncSetAttribute(gemm_bf16<2>, cudaFuncAttributeMaxDynamicSharedMemorySize, G_SMEM_BYTES);

    cvt_bf16<<<1728, 256>>>(qkv_w, wq, 442368);
    cvt_bf16<<<576, 256>>>(proj_w, wp, 147456);
    ln_kernel<<<576, 256>>>(x, n1w, n1b, xnb);
    gemm_bf16<0><<<dim3(36, 18), 256, G_SMEM_BYTES>>>(xnb, wq, qkv_b, qkvf, 768, 2304, nullptr, nullptr);
    attn_mma2<<<dim3(37, 12), 256>>>(qkvf, attnb);
    gemm_bf16<2><<<dim3(36, 6), 256, G_SMEM_BYTES>>>(attnb, wp, proj_b, x1, 768, 768, x, ls1);
    cvt_bf16<<<2304, 256>>>(fc1_w, w1, 589824);
    cvt_bf16<<<2304, 256>>>(fc2_w, w2, 589824);
    ln_kernel<<<576, 256>>>(x1, n2w, n2b, xnb);
    gemm_bf16<1><<<dim3(36, 24), 256, G_SMEM_BYTES>>>(xnb, w1, fc1_b, hb, 768, 3072, nullptr, nullptr);
    gemm_bf16<2><<<dim3(36, 6), 256, G_SMEM_BYTES>>>(hb, w2, fc2_b, out, 3072, 768, x1, ls2);
}